// round 3
// baseline (speedup 1.0000x reference)
#include <cuda_runtime.h>
#include <math.h>

#define BATCH 4
#define SEQ 1024
#define DMODEL 2048
#define KVD 512
#define NHEADS 16
#define NGROUPS 4
#define HDIM 128
#define ROWS (BATCH*SEQ)           // 4096
#define SOFTMAX_SCALE 0.08838834764831845f   // 1/sqrt(128)

// Scratch (device globals — no allocation allowed)
__device__ float g_Q[ROWS*DMODEL];   // 32 MB
__device__ float g_K[ROWS*KVD];      // 8 MB
__device__ float g_V[ROWS*KVD];      // 8 MB
__device__ float g_O[ROWS*DMODEL];   // 32 MB

// ---------------------------------------------------------------------------
// Tiled SGEMM: C[M,N] = A[M,K] @ B[K,N] + bias[N]
// 128x128 block tile, BK=8, 256 threads, 8x8 per thread.
// ---------------------------------------------------------------------------
__global__ __launch_bounds__(256) void sgemm_bias(
    const float* __restrict__ A, const float* __restrict__ Bm,
    const float* __restrict__ bias, float* __restrict__ C,
    int M, int N, int K)
{
    __shared__ float As[8][128];
    __shared__ float Bs[8][128];
    const int tid = threadIdx.x;
    const int bm = blockIdx.y * 128;
    const int bn = blockIdx.x * 128;
    const int row = (tid >> 4) * 8;     // 0..120
    const int col = (tid & 15) * 8;     // 0..120

    float acc[8][8];
#pragma unroll
    for (int i = 0; i < 8; i++)
#pragma unroll
        for (int j = 0; j < 8; j++) acc[i][j] = 0.f;

    const int arow = tid >> 1;          // 0..127
    const int acol = (tid & 1) * 4;     // 0 or 4
    const int brow = tid >> 5;          // 0..7
    const int bcol = (tid & 31) * 4;    // 0..124

    const float* Aptr = A + (size_t)(bm + arow) * K + acol;
    const float* Bptr = Bm + (size_t)brow * N + bn + bcol;

    for (int k0 = 0; k0 < K; k0 += 8) {
        float4 av = *(const float4*)(Aptr); Aptr += 8;
        float4 bv = *(const float4*)(Bptr + (size_t)k0 * N);
        As[acol + 0][arow] = av.x;
        As[acol + 1][arow] = av.y;
        As[acol + 2][arow] = av.z;
        As[acol + 3][arow] = av.w;
        *(float4*)&Bs[brow][bcol] = bv;
        __syncthreads();
#pragma unroll
        for (int kk = 0; kk < 8; kk++) {
            float a[8], b[8];
#pragma unroll
            for (int i = 0; i < 8; i++) a[i] = As[kk][row + i];
#pragma unroll
            for (int j = 0; j < 8; j++) b[j] = Bs[kk][col + j];
#pragma unroll
            for (int i = 0; i < 8; i++)
#pragma unroll
                for (int j = 0; j < 8; j++)
                    acc[i][j] = fmaf(a[i], b[j], acc[i][j]);
        }
        __syncthreads();
    }

#pragma unroll
    for (int i = 0; i < 8; i++) {
        float* crow = C + (size_t)(bm + row + i) * N + bn + col;
#pragma unroll
        for (int j = 0; j < 8; j++)
            crow[j] = acc[i][j] + bias[bn + col + j];
    }
}

// ---------------------------------------------------------------------------
// RoPE (in place). X: [ROWS, nh*128]. One thread per (row, head, freq-pair).
// ---------------------------------------------------------------------------
__global__ void rope_kernel(float* __restrict__ X, int nh, float scale, int total)
{
    int idx = blockIdx.x * blockDim.x + threadIdx.x;
    if (idx >= total) return;
    const int ppr = nh * 64;            // pairs per row
    int r   = idx / ppr;
    int rem = idx - r * ppr;
    int h = rem >> 6;
    int i = rem & 63;
    int pos = r & (SEQ - 1);

    // inv_freq = 10000^(-2i/128) = 2^(-(2i/128)*log2(10000))
    float freq = exp2f(-((float)(2 * i) / 128.0f) * 13.287712379549449f);
    float ang = (float)pos * freq;
    float s, c;
    sincosf(ang, &s, &c);

    float* p = X + (size_t)r * (nh * HDIM) + h * HDIM + 2 * i;
    float x1 = p[0], x2 = p[1];
    p[0] = (x1 * c - x2 * s) * scale;
    p[1] = (x1 * s + x2 * c) * scale;
}

// ---------------------------------------------------------------------------
// Flash attention (full mask, non-causal). Block: 64 q-rows of one (b,h).
// 256 threads. Key tiles of 64. K/V share one smem buffer.
// Smem: Qt[128][68], KV[128][68] (K transposed / V row-major [64][132]),
//       Ss[64][68], row stats.
// ---------------------------------------------------------------------------
#define ATT_QTP 68
#define ATT_VP  132
#define ATT_SMEM_FLOATS (128*ATT_QTP + 128*ATT_QTP + 64*68 + 192)
#define ATT_SMEM_BYTES  (ATT_SMEM_FLOATS * 4)

__global__ __launch_bounds__(256) void attn_kernel()
{
    extern __shared__ float sm[];
    float* Qt    = sm;                       // [128][68] : Qt[d][q]
    float* KV    = Qt + 128 * ATT_QTP;       // Kt[d][j] (68) OR Vs[j][d] (132)
    float* Ss    = KV + 128 * ATT_QTP;       // [64][68]
    float* row_m = Ss + 64 * 68;
    float* row_l = row_m + 64;
    float* row_f = row_l + 64;

    const int tid = threadIdx.x;
    const int bh = blockIdx.x;
    const int b = bh >> 4;
    const int h = bh & 15;
    const int g = h >> 2;                    // KV group
    const int q0 = blockIdx.y * 64;

    const float* Qg = g_Q + (size_t)(b * SEQ + q0) * DMODEL + h * HDIM;
    const float* Kg = g_K + (size_t)(b * SEQ) * KVD + g * HDIM;
    const float* Vg = g_V + (size_t)(b * SEQ) * KVD + g * HDIM;

    // Load Q tile transposed: 64 rows x 128 dims = 2048 float4 / 256 thr = 8 ea
#pragma unroll
    for (int it = 0; it < 8; it++) {
        int idx = tid + it * 256;            // 0..2047
        int q = idx >> 5;                    // 0..63
        int d4 = (idx & 31) * 4;             // 0..124
        float4 v = *(const float4*)(Qg + (size_t)q * DMODEL + d4);
        Qt[(d4 + 0) * ATT_QTP + q] = v.x;
        Qt[(d4 + 1) * ATT_QTP + q] = v.y;
        Qt[(d4 + 2) * ATT_QTP + q] = v.z;
        Qt[(d4 + 3) * ATT_QTP + q] = v.w;
    }
    if (tid < 64) {
        row_m[tid] = -INFINITY;
        row_l[tid] = 0.f;
    }

    const int ty = tid >> 4;                 // 0..15
    const int tx = tid & 15;                 // 0..15
    const int orow = ty * 4;                 // O rows (4)
    const int ocol = tx * 8;                 // O cols (8)

    float acc[4][8];
#pragma unroll
    for (int i = 0; i < 4; i++)
#pragma unroll
        for (int c = 0; c < 8; c++) acc[i][c] = 0.f;

    for (int kt = 0; kt < SEQ / 64; kt++) {
        __syncthreads();   // previous PV reads of KV/Ss done

        // Load K tile transposed into KV
        const float* Kgt = Kg + (size_t)(kt * 64) * KVD;
#pragma unroll
        for (int it = 0; it < 8; it++) {
            int idx = tid + it * 256;
            int j = idx >> 5;
            int d4 = (idx & 31) * 4;
            float4 v = *(const float4*)(Kgt + (size_t)j * KVD + d4);
            KV[(d4 + 0) * ATT_QTP + j] = v.x;
            KV[(d4 + 1) * ATT_QTP + j] = v.y;
            KV[(d4 + 2) * ATT_QTP + j] = v.z;
            KV[(d4 + 3) * ATT_QTP + j] = v.w;
        }
        __syncthreads();

        // S = Qt^T * Kt : each thread 4x4
        float sacc[4][4];
#pragma unroll
        for (int i = 0; i < 4; i++)
#pragma unroll
            for (int j = 0; j < 4; j++) sacc[i][j] = 0.f;

#pragma unroll 8
        for (int d = 0; d < 128; d++) {
            float a[4], bb[4];
#pragma unroll
            for (int i = 0; i < 4; i++) a[i] = Qt[d * ATT_QTP + ty * 4 + i];
#pragma unroll
            for (int j = 0; j < 4; j++) bb[j] = KV[d * ATT_QTP + tx * 4 + j];
#pragma unroll
            for (int i = 0; i < 4; i++)
#pragma unroll
                for (int j = 0; j < 4; j++)
                    sacc[i][j] = fmaf(a[i], bb[j], sacc[i][j]);
        }
#pragma unroll
        for (int i = 0; i < 4; i++)
#pragma unroll
            for (int j = 0; j < 4; j++)
                Ss[(ty * 4 + i) * 68 + tx * 4 + j] = sacc[i][j] * SOFTMAX_SCALE;

        __syncthreads();   // S reads of KV finished; Ss complete

        // Load V tile into KV (row-major [64][132])
        const float* Vgt = Vg + (size_t)(kt * 64) * KVD;
#pragma unroll
        for (int it = 0; it < 8; it++) {
            int idx = tid + it * 256;
            int j = idx >> 5;
            int d4 = (idx & 31) * 4;
            float4 v = *(const float4*)(Vgt + (size_t)j * KVD + d4);
            *(float4*)&KV[j * ATT_VP + d4] = v;
        }

        // Online softmax (one thread per q row)
        if (tid < 64) {
            int r = tid;
            float m_old = row_m[r];
            float mx = m_old;
#pragma unroll 8
            for (int j = 0; j < 64; j++) mx = fmaxf(mx, Ss[r * 68 + j]);
            float f = __expf(m_old - mx);
            float l = row_l[r] * f;
#pragma unroll 8
            for (int j = 0; j < 64; j++) {
                float p = __expf(Ss[r * 68 + j] - mx);
                Ss[r * 68 + j] = p;
                l += p;
            }
            row_m[r] = mx;
            row_l[r] = l;
            row_f[r] = f;
        }
        __syncthreads();   // V loaded, softmax done

        // Rescale accumulator and accumulate P @ V
        float fr[4];
#pragma unroll
        for (int i = 0; i < 4; i++) fr[i] = row_f[orow + i];
#pragma unroll
        for (int i = 0; i < 4; i++)
#pragma unroll
            for (int c = 0; c < 8; c++) acc[i][c] *= fr[i];

#pragma unroll 8
        for (int j = 0; j < 64; j++) {
            float p[4], v[8];
#pragma unroll
            for (int i = 0; i < 4; i++) p[i] = Ss[(orow + i) * 68 + j];
#pragma unroll
            for (int c = 0; c < 8; c++) v[c] = KV[j * ATT_VP + ocol + c];
#pragma unroll
            for (int i = 0; i < 4; i++)
#pragma unroll
                for (int c = 0; c < 8; c++)
                    acc[i][c] = fmaf(p[i], v[c], acc[i][c]);
        }
    }

    // Normalize and write O (row-major [ROWS, 2048], heads concatenated)
    float* Og = g_O + (size_t)(b * SEQ + q0) * DMODEL + h * HDIM;
#pragma unroll
    for (int i = 0; i < 4; i++) {
        float inv = 1.0f / row_l[orow + i];
#pragma unroll
        for (int c = 0; c < 8; c++)
            Og[(size_t)(orow + i) * DMODEL + ocol + c] = acc[i][c] * inv;
    }
}

// ---------------------------------------------------------------------------
extern "C" void kernel_launch(void* const* d_in, const int* in_sizes, int n_in,
                              void* d_out, int out_size)
{
    const float* x  = (const float*)d_in[0];
    const float* Wq = (const float*)d_in[1];
    const float* bq = (const float*)d_in[2];
    const float* Wk = (const float*)d_in[3];
    const float* bk = (const float*)d_in[4];
    const float* Wv = (const float*)d_in[5];
    const float* bv = (const float*)d_in[6];
    const float* Wo = (const float*)d_in[7];
    const float* bo = (const float*)d_in[8];
    // d_in[9] = mask: all ones, ignored
    float* out = (float*)d_out;

    float *Q, *K, *V, *O;
    cudaGetSymbolAddress((void**)&Q, g_Q);
    cudaGetSymbolAddress((void**)&K, g_K);
    cudaGetSymbolAddress((void**)&V, g_V);
    cudaGetSymbolAddress((void**)&O, g_O);

    cudaFuncSetAttribute(attn_kernel,
                         cudaFuncAttributeMaxDynamicSharedMemorySize,
                         ATT_SMEM_BYTES);

    // QKV projections
    sgemm_bias<<<dim3(DMODEL/128, ROWS/128), 256>>>(x, Wq, bq, Q, ROWS, DMODEL, DMODEL);
    sgemm_bias<<<dim3(KVD/128,    ROWS/128), 256>>>(x, Wk, bk, K, ROWS, KVD, DMODEL);
    sgemm_bias<<<dim3(KVD/128,    ROWS/128), 256>>>(x, Wv, bv, V, ROWS, KVD, DMODEL);

    // RoPE (Q gets the explicit head_dim^-0.5 from the reference)
    {
        int totQ = ROWS * NHEADS * 64;
        int totK = ROWS * NGROUPS * 64;
        rope_kernel<<<(totQ + 255) / 256, 256>>>(Q, NHEADS, SOFTMAX_SCALE, totQ);
        rope_kernel<<<(totK + 255) / 256, 256>>>(K, NGROUPS, 1.0f, totK);
    }

    // Attention
    attn_kernel<<<dim3(BATCH * NHEADS, SEQ / 64), 256, ATT_SMEM_BYTES>>>();

    // Output projection
    sgemm_bias<<<dim3(DMODEL/128, ROWS/128), 256>>>(O, Wo, bo, out, ROWS, DMODEL, DMODEL);
}

// round 7
// speedup vs baseline: 3.2928x; 3.2928x over previous
#include <cuda_runtime.h>
#include <math.h>
#include <stdint.h>

#define BATCH 4
#define SEQ 1024
#define DMODEL 2048
#define KVD 512
#define NHEADS 16
#define NGROUPS 4
#define HDIM 128
#define ROWS (BATCH*SEQ)           // 4096
#define SOFTMAX_SCALE 0.08838834764831845f   // 1/sqrt(128)

// ---------------------------------------------------------------------------
// Device scratch (no allocation allowed)
// ---------------------------------------------------------------------------
__device__ float g_Q[ROWS*DMODEL];     // 32 MB
__device__ float g_K[ROWS*KVD];        // 8 MB
__device__ float g_V[ROWS*KVD];        // 8 MB
__device__ float g_O[ROWS*DMODEL];     // 32 MB
__device__ float g_WqT[DMODEL*DMODEL]; // 16 MB  [N][K]
__device__ float g_WkT[KVD*DMODEL];    // 4 MB
__device__ float g_WvT[KVD*DMODEL];    // 4 MB
__device__ float g_WoT[DMODEL*DMODEL]; // 16 MB

// ---------------------------------------------------------------------------
// PTX helpers (sm_80-class only — NO tcgen05, harness targets bare sm_103)
// ---------------------------------------------------------------------------
__device__ __forceinline__ uint32_t smem_u32(const void* p) {
    uint32_t a;
    asm("{ .reg .u64 t; cvta.to.shared.u64 t, %1; cvt.u32.u64 %0, t; }"
        : "=r"(a) : "l"(p));
    return a;
}

__device__ __forceinline__ void cp16(uint32_t dst, const void* src) {
    asm volatile("cp.async.cg.shared.global [%0], [%1], 16;" :: "r"(dst), "l"(src));
}

#define LDSM_X4(r0, r1, r2, r3, addr) \
    asm volatile("ldmatrix.sync.aligned.m8n8.x4.shared.b16 {%0,%1,%2,%3}, [%4];" \
        : "=r"(r0), "=r"(r1), "=r"(r2), "=r"(r3) : "r"(addr))

#define CVT_TF32(x) asm volatile("cvt.rna.tf32.f32 %0, %0;" : "+r"(x))

#define MMA_TF32(d, a0, a1, a2, a3, b0, b1) \
    asm volatile("mma.sync.aligned.m16n8k8.row.col.f32.tf32.tf32.f32 " \
        "{%0,%1,%2,%3}, {%4,%5,%6,%7}, {%8,%9}, {%0,%1,%2,%3};" \
        : "+f"((d)[0]), "+f"((d)[1]), "+f"((d)[2]), "+f"((d)[3]) \
        : "r"(a0), "r"(a1), "r"(a2), "r"(a3), "r"(b0), "r"(b1))

// ---------------------------------------------------------------------------
// Weight transpose: in [R][C] -> out [C][R]
// ---------------------------------------------------------------------------
__global__ void transpose_kernel(const float* __restrict__ in, float* __restrict__ out,
                                 int R, int C)
{
    __shared__ float t[32][33];
    int c0 = blockIdx.x * 32, r0 = blockIdx.y * 32;
    int x = threadIdx.x, y = threadIdx.y;  // 32 x 8
#pragma unroll
    for (int i = 0; i < 32; i += 8)
        t[y + i][x] = in[(size_t)(r0 + y + i) * C + c0 + x];
    __syncthreads();
#pragma unroll
    for (int i = 0; i < 32; i += 8)
        out[(size_t)(c0 + y + i) * R + r0 + x] = t[x][y + i];
}

// ---------------------------------------------------------------------------
// tf32 mma.sync GEMM: C[M,N] = A[M,K] @ BT[N,K]^T + bias
// CTA tile 128x128, BK=32 (128B swizzled rows), double-buffered cp.async.
// 8 warps in 2(M)x4(N); warp tile 64x32 = 4x4 m16n8k8 fragments.
// Smem: buf b at b*32768: A[128][32] (16KB) then BT[128][32] (16KB). 64KB.
// ---------------------------------------------------------------------------
#define GM_SMEM 65536

__global__ __launch_bounds__(256) void tf32_mma_gemm(
    const float* __restrict__ A, const float* __restrict__ BT,
    const float* __restrict__ bias, float* __restrict__ C,
    int M, int N, int K)
{
    extern __shared__ char sm[];
    const uint32_t sb = smem_u32(sm);
    const int tid = threadIdx.x;
    const int wid = tid >> 5, lid = tid & 31;
    const int bm = blockIdx.y * 128;
    const int bn = blockIdx.x * 128;
    const int wm = (wid >> 2) * 64;      // warp M offset in tile
    const int wn = (wid & 3) * 32;       // warp N offset in tile

    // cp.async loader indices: 2048 16B-chunks per (A+B) tile, 8 per thread
    const int ld_row = tid >> 3;         // used per-iteration below
    (void)ld_row;

    // LDSM per-thread geometry (see fragment-layout derivation)
    const uint32_t xr     = lid & 7;                       // smem row & 7
    const uint32_t a_row  = wm + (lid & 15);               // + mi*16
    const uint32_t a_cadd = (lid >= 16) ? 4u : 0u;         // tf32 col offset
    const uint32_t b_row  = wn + ((lid >> 4) << 3) + (lid & 7);  // + nb*16
    const uint32_t b_cadd = ((lid >> 3) & 1) * 4u;

    float acc[4][4][4];
#pragma unroll
    for (int mi = 0; mi < 4; mi++)
#pragma unroll
        for (int nj = 0; nj < 4; nj++)
#pragma unroll
            for (int r = 0; r < 4; r++) acc[mi][nj][r] = 0.f;

    const int nk = K >> 5;               // K/32

    // ---- tile loader (issues one cp.async group) ----
    auto load_tile = [&](int buf, int ks) {
        const uint32_t abuf = sb + buf * 32768;
        const uint32_t bbuf = abuf + 16384;
        const int k0 = ks * 32;
#pragma unroll
        for (int it = 0; it < 8; it++) {
            int idx = tid + it * 256;            // 0..2047
            int c = idx & 7;
            if (idx < 1024) {
                int row = idx >> 3;              // 0..127
                cp16(abuf + row * 128 + ((c ^ (row & 7)) << 4),
                     A + (size_t)(bm + row) * K + k0 + c * 4);
            } else {
                int row = (idx - 1024) >> 3;     // 0..127
                cp16(bbuf + row * 128 + ((c ^ (row & 7)) << 4),
                     BT + (size_t)(bn + row) * K + k0 + c * 4);
            }
        }
        asm volatile("cp.async.commit_group;" ::: "memory");
    };

    load_tile(0, 0);

    for (int ks = 0; ks < nk; ks++) {
        const int buf = ks & 1;
        if (ks + 1 < nk) {
            load_tile(buf ^ 1, ks + 1);
            asm volatile("cp.async.wait_group 1;" ::: "memory");
        } else {
            asm volatile("cp.async.wait_group 0;" ::: "memory");
        }
        __syncthreads();

        const uint32_t abase = sb + buf * 32768;
        const uint32_t bbase = abase + 16384;

#pragma unroll
        for (int s = 0; s < 4; s++) {
            const int k0 = s * 8;
            uint32_t ar[4][4];
#pragma unroll
            for (int mi = 0; mi < 4; mi++) {
                uint32_t addr = abase + (a_row + mi * 16) * 128
                              + ((((k0 + a_cadd) >> 2) ^ xr) << 4);
                LDSM_X4(ar[mi][0], ar[mi][1], ar[mi][2], ar[mi][3], addr);
                CVT_TF32(ar[mi][0]); CVT_TF32(ar[mi][1]);
                CVT_TF32(ar[mi][2]); CVT_TF32(ar[mi][3]);
            }
            uint32_t br[2][4];
#pragma unroll
            for (int nb = 0; nb < 2; nb++) {
                uint32_t addr = bbase + (b_row + nb * 16) * 128
                              + ((((k0 + b_cadd) >> 2) ^ xr) << 4);
                LDSM_X4(br[nb][0], br[nb][1], br[nb][2], br[nb][3], addr);
                CVT_TF32(br[nb][0]); CVT_TF32(br[nb][1]);
                CVT_TF32(br[nb][2]); CVT_TF32(br[nb][3]);
            }
#pragma unroll
            for (int mi = 0; mi < 4; mi++)
#pragma unroll
                for (int nj = 0; nj < 4; nj++) {
                    uint32_t b0 = br[nj >> 1][(nj & 1) * 2];
                    uint32_t b1 = br[nj >> 1][(nj & 1) * 2 + 1];
                    MMA_TF32(acc[mi][nj], ar[mi][0], ar[mi][1], ar[mi][2], ar[mi][3], b0, b1);
                }
        }
        __syncthreads();
    }

    // ---- epilogue: direct global float2 stores + bias ----
    const int tq = lid >> 2;            // 0..7
    const int tc = (lid & 3) * 2;       // 0,2,4,6
#pragma unroll
    for (int mi = 0; mi < 4; mi++) {
        const int row = bm + wm + mi * 16 + tq;
#pragma unroll
        for (int nj = 0; nj < 4; nj++) {
            const int col = bn + wn + nj * 8 + tc;
            float2 bv = *(const float2*)(bias + col);
            float2 o0 = { acc[mi][nj][0] + bv.x, acc[mi][nj][1] + bv.y };
            float2 o1 = { acc[mi][nj][2] + bv.x, acc[mi][nj][3] + bv.y };
            *(float2*)(C + (size_t)row * N + col)       = o0;
            *(float2*)(C + (size_t)(row + 8) * N + col) = o1;
        }
    }
}

// ---------------------------------------------------------------------------
// RoPE (in place). X: [ROWS, nh*128].
// ---------------------------------------------------------------------------
__global__ void rope_kernel(float* __restrict__ X, int nh, float scale, int total)
{
    int idx = blockIdx.x * blockDim.x + threadIdx.x;
    if (idx >= total) return;
    const int ppr = nh * 64;
    int r   = idx / ppr;
    int rem = idx - r * ppr;
    int h = rem >> 6;
    int i = rem & 63;
    int pos = r & (SEQ - 1);

    float freq = exp2f(-((float)(2 * i) / 128.0f) * 13.287712379549449f);
    float ang = (float)pos * freq;
    float s, c;
    sincosf(ang, &s, &c);

    float* p = X + (size_t)r * (nh * HDIM) + h * HDIM + 2 * i;
    float x1 = p[0], x2 = p[1];
    p[0] = (x1 * c - x2 * s) * scale;
    p[1] = (x1 * s + x2 * c) * scale;
}

// ---------------------------------------------------------------------------
// Flash attention (fp32, proven baseline)
// ---------------------------------------------------------------------------
#define ATT_QTP 68
#define ATT_VP  132
#define ATT_SMEM_FLOATS (128*ATT_QTP + 128*ATT_QTP + 64*68 + 192)
#define ATT_SMEM_BYTES  (ATT_SMEM_FLOATS * 4)

__global__ __launch_bounds__(256) void attn_kernel()
{
    extern __shared__ float smf[];
    float* Qt    = smf;
    float* KV    = Qt + 128 * ATT_QTP;
    float* Ss    = KV + 128 * ATT_QTP;
    float* row_m = Ss + 64 * 68;
    float* row_l = row_m + 64;
    float* row_f = row_l + 64;

    const int tid = threadIdx.x;
    const int bh = blockIdx.x;
    const int b = bh >> 4;
    const int h = bh & 15;
    const int g = h >> 2;
    const int q0 = blockIdx.y * 64;

    const float* Qg = g_Q + (size_t)(b * SEQ + q0) * DMODEL + h * HDIM;
    const float* Kg = g_K + (size_t)(b * SEQ) * KVD + g * HDIM;
    const float* Vg = g_V + (size_t)(b * SEQ) * KVD + g * HDIM;

#pragma unroll
    for (int it = 0; it < 8; it++) {
        int idx = tid + it * 256;
        int q = idx >> 5;
        int d4 = (idx & 31) * 4;
        float4 v = *(const float4*)(Qg + (size_t)q * DMODEL + d4);
        Qt[(d4 + 0) * ATT_QTP + q] = v.x;
        Qt[(d4 + 1) * ATT_QTP + q] = v.y;
        Qt[(d4 + 2) * ATT_QTP + q] = v.z;
        Qt[(d4 + 3) * ATT_QTP + q] = v.w;
    }
    if (tid < 64) {
        row_m[tid] = -INFINITY;
        row_l[tid] = 0.f;
    }

    const int ty = tid >> 4;
    const int tx = tid & 15;
    const int orow = ty * 4;
    const int ocol = tx * 8;

    float acc[4][8];
#pragma unroll
    for (int i = 0; i < 4; i++)
#pragma unroll
        for (int c = 0; c < 8; c++) acc[i][c] = 0.f;

    for (int kt = 0; kt < SEQ / 64; kt++) {
        __syncthreads();

        const float* Kgt = Kg + (size_t)(kt * 64) * KVD;
#pragma unroll
        for (int it = 0; it < 8; it++) {
            int idx = tid + it * 256;
            int j = idx >> 5;
            int d4 = (idx & 31) * 4;
            float4 v = *(const float4*)(Kgt + (size_t)j * KVD + d4);
            KV[(d4 + 0) * ATT_QTP + j] = v.x;
            KV[(d4 + 1) * ATT_QTP + j] = v.y;
            KV[(d4 + 2) * ATT_QTP + j] = v.z;
            KV[(d4 + 3) * ATT_QTP + j] = v.w;
        }
        __syncthreads();

        float sacc[4][4];
#pragma unroll
        for (int i = 0; i < 4; i++)
#pragma unroll
            for (int j = 0; j < 4; j++) sacc[i][j] = 0.f;

#pragma unroll 8
        for (int d = 0; d < 128; d++) {
            float a[4], bb[4];
#pragma unroll
            for (int i = 0; i < 4; i++) a[i] = Qt[d * ATT_QTP + ty * 4 + i];
#pragma unroll
            for (int j = 0; j < 4; j++) bb[j] = KV[d * ATT_QTP + tx * 4 + j];
#pragma unroll
            for (int i = 0; i < 4; i++)
#pragma unroll
                for (int j = 0; j < 4; j++)
                    sacc[i][j] = fmaf(a[i], bb[j], sacc[i][j]);
        }
#pragma unroll
        for (int i = 0; i < 4; i++)
#pragma unroll
            for (int j = 0; j < 4; j++)
                Ss[(ty * 4 + i) * 68 + tx * 4 + j] = sacc[i][j] * SOFTMAX_SCALE;

        __syncthreads();

        const float* Vgt = Vg + (size_t)(kt * 64) * KVD;
#pragma unroll
        for (int it = 0; it < 8; it++) {
            int idx = tid + it * 256;
            int j = idx >> 5;
            int d4 = (idx & 31) * 4;
            float4 v = *(const float4*)(Vgt + (size_t)j * KVD + d4);
            *(float4*)&KV[j * ATT_VP + d4] = v;
        }

        if (tid < 64) {
            int r = tid;
            float m_old = row_m[r];
            float mx = m_old;
#pragma unroll 8
            for (int j = 0; j < 64; j++) mx = fmaxf(mx, Ss[r * 68 + j]);
            float f = __expf(m_old - mx);
            float l = row_l[r] * f;
#pragma unroll 8
            for (int j = 0; j < 64; j++) {
                float p = __expf(Ss[r * 68 + j] - mx);
                Ss[r * 68 + j] = p;
                l += p;
            }
            row_m[r] = mx;
            row_l[r] = l;
            row_f[r] = f;
        }
        __syncthreads();

        float fr[4];
#pragma unroll
        for (int i = 0; i < 4; i++) fr[i] = row_f[orow + i];
#pragma unroll
        for (int i = 0; i < 4; i++)
#pragma unroll
            for (int c = 0; c < 8; c++) acc[i][c] *= fr[i];

#pragma unroll 8
        for (int j = 0; j < 64; j++) {
            float p[4], v[8];
#pragma unroll
            for (int i = 0; i < 4; i++) p[i] = Ss[(orow + i) * 68 + j];
#pragma unroll
            for (int c = 0; c < 8; c++) v[c] = KV[j * ATT_VP + ocol + c];
#pragma unroll
            for (int i = 0; i < 4; i++)
#pragma unroll
                for (int c = 0; c < 8; c++)
                    acc[i][c] = fmaf(p[i], v[c], acc[i][c]);
        }
    }

    float* Og = g_O + (size_t)(b * SEQ + q0) * DMODEL + h * HDIM;
#pragma unroll
    for (int i = 0; i < 4; i++) {
        float inv = 1.0f / row_l[orow + i];
#pragma unroll
        for (int c = 0; c < 8; c++)
            Og[(size_t)(orow + i) * DMODEL + ocol + c] = acc[i][c] * inv;
    }
}

// ---------------------------------------------------------------------------
extern "C" void kernel_launch(void* const* d_in, const int* in_sizes, int n_in,
                              void* d_out, int out_size)
{
    const float* x  = (const float*)d_in[0];
    const float* Wq = (const float*)d_in[1];
    const float* bq = (const float*)d_in[2];
    const float* Wk = (const float*)d_in[3];
    const float* bk = (const float*)d_in[4];
    const float* Wv = (const float*)d_in[5];
    const float* bv = (const float*)d_in[6];
    const float* Wo = (const float*)d_in[7];
    const float* bo = (const float*)d_in[8];
    float* out = (float*)d_out;

    float *Q, *K, *V, *O, *WqT, *WkT, *WvT, *WoT;
    cudaGetSymbolAddress((void**)&Q, g_Q);
    cudaGetSymbolAddress((void**)&K, g_K);
    cudaGetSymbolAddress((void**)&V, g_V);
    cudaGetSymbolAddress((void**)&O, g_O);
    cudaGetSymbolAddress((void**)&WqT, g_WqT);
    cudaGetSymbolAddress((void**)&WkT, g_WkT);
    cudaGetSymbolAddress((void**)&WvT, g_WvT);
    cudaGetSymbolAddress((void**)&WoT, g_WoT);

    cudaFuncSetAttribute(tf32_mma_gemm,
                         cudaFuncAttributeMaxDynamicSharedMemorySize, GM_SMEM);
    cudaFuncSetAttribute(attn_kernel,
                         cudaFuncAttributeMaxDynamicSharedMemorySize, ATT_SMEM_BYTES);

    // Transpose weights to [N][K]
    transpose_kernel<<<dim3(DMODEL/32, DMODEL/32), dim3(32, 8)>>>(Wq, WqT, DMODEL, DMODEL);
    transpose_kernel<<<dim3(KVD/32,    DMODEL/32), dim3(32, 8)>>>(Wk, WkT, DMODEL, KVD);
    transpose_kernel<<<dim3(KVD/32,    DMODEL/32), dim3(32, 8)>>>(Wv, WvT, DMODEL, KVD);
    transpose_kernel<<<dim3(DMODEL/32, DMODEL/32), dim3(32, 8)>>>(Wo, WoT, DMODEL, DMODEL);

    // QKV projections (tf32 mma.sync)
    tf32_mma_gemm<<<dim3(DMODEL/128, ROWS/128), 256, GM_SMEM>>>(x, WqT, bq, Q, ROWS, DMODEL, DMODEL);
    tf32_mma_gemm<<<dim3(KVD/128,    ROWS/128), 256, GM_SMEM>>>(x, WkT, bk, K, ROWS, KVD, DMODEL);
    tf32_mma_gemm<<<dim3(KVD/128,    ROWS/128), 256, GM_SMEM>>>(x, WvT, bv, V, ROWS, KVD, DMODEL);

    // RoPE (Q gets head_dim^-0.5)
    {
        int totQ = ROWS * NHEADS * 64;
        int totK = ROWS * NGROUPS * 64;
        rope_kernel<<<(totQ + 255) / 256, 256>>>(Q, NHEADS, SOFTMAX_SCALE, totQ);
        rope_kernel<<<(totK + 255) / 256, 256>>>(K, NGROUPS, 1.0f, totK);
    }

    // Attention (fp32 flash)
    attn_kernel<<<dim3(BATCH * NHEADS, SEQ / 64), 256, ATT_SMEM_BYTES>>>();

    // Output projection (tf32 mma.sync)
    tf32_mma_gemm<<<dim3(DMODEL/128, ROWS/128), 256, GM_SMEM>>>(O, WoT, bo, out, ROWS, DMODEL, DMODEL);
}

// round 10
// speedup vs baseline: 6.4360x; 1.9546x over previous
#include <cuda_runtime.h>
#include <math.h>
#include <stdint.h>

#define BATCH 4
#define SEQ 1024
#define DMODEL 2048
#define KVD 512
#define NHEADS 16
#define NGROUPS 4
#define HDIM 128
#define ROWS (BATCH*SEQ)           // 4096
#define SOFTMAX_SCALE 0.08838834764831845f   // 1/sqrt(128)

// ---------------------------------------------------------------------------
// Device scratch (no allocation allowed)
// ---------------------------------------------------------------------------
__device__ float g_Q[ROWS*DMODEL];     // 32 MB
__device__ float g_K[ROWS*KVD];        // 8 MB
__device__ float g_V[ROWS*KVD];        // 8 MB
__device__ float g_O[ROWS*DMODEL];     // 32 MB
__device__ float g_WqT[DMODEL*DMODEL]; // 16 MB  [N][K]
__device__ float g_WkT[KVD*DMODEL];    // 4 MB
__device__ float g_WvT[KVD*DMODEL];    // 4 MB
__device__ float g_WoT[DMODEL*DMODEL]; // 16 MB

// ---------------------------------------------------------------------------
// PTX helpers (sm_80-class only — NO tcgen05, harness targets bare sm_103)
// ---------------------------------------------------------------------------
__device__ __forceinline__ uint32_t smem_u32(const void* p) {
    uint32_t a;
    asm("{ .reg .u64 t; cvta.to.shared.u64 t, %1; cvt.u32.u64 %0, t; }"
        : "=r"(a) : "l"(p));
    return a;
}

__device__ __forceinline__ void cp16(uint32_t dst, const void* src) {
    asm volatile("cp.async.cg.shared.global [%0], [%1], 16;" :: "r"(dst), "l"(src));
}

#define LDSM_X4(r0, r1, r2, r3, addr) \
    asm volatile("ldmatrix.sync.aligned.m8n8.x4.shared.b16 {%0,%1,%2,%3}, [%4];" \
        : "=r"(r0), "=r"(r1), "=r"(r2), "=r"(r3) : "r"(addr))

#define CVT_TF32(x) asm volatile("cvt.rna.tf32.f32 %0, %0;" : "+r"(x))

#define MMA_TF32(d, a0, a1, a2, a3, b0, b1) \
    asm volatile("mma.sync.aligned.m16n8k8.row.col.f32.tf32.tf32.f32 " \
        "{%0,%1,%2,%3}, {%4,%5,%6,%7}, {%8,%9}, {%0,%1,%2,%3};" \
        : "+f"((d)[0]), "+f"((d)[1]), "+f"((d)[2]), "+f"((d)[3]) \
        : "r"(a0), "r"(a1), "r"(a2), "r"(a3), "r"(b0), "r"(b1))

// ---------------------------------------------------------------------------
// Weight transpose: in [R][C] -> out [C][R]
// ---------------------------------------------------------------------------
__global__ void transpose_kernel(const float* __restrict__ in, float* __restrict__ out,
                                 int R, int C)
{
    __shared__ float t[32][33];
    int c0 = blockIdx.x * 32, r0 = blockIdx.y * 32;
    int x = threadIdx.x, y = threadIdx.y;  // 32 x 8
#pragma unroll
    for (int i = 0; i < 32; i += 8)
        t[y + i][x] = in[(size_t)(r0 + y + i) * C + c0 + x];
    __syncthreads();
#pragma unroll
    for (int i = 0; i < 32; i += 8)
        out[(size_t)(c0 + y + i) * R + r0 + x] = t[x][y + i];
}

// ---------------------------------------------------------------------------
// tf32 mma.sync GEMM: C[M,N] = A[M,K] @ BT[N,K]^T + bias  (proven in R7)
// ---------------------------------------------------------------------------
#define GM_SMEM 65536

__global__ __launch_bounds__(256) void tf32_mma_gemm(
    const float* __restrict__ A, const float* __restrict__ BT,
    const float* __restrict__ bias, float* __restrict__ C,
    int M, int N, int K)
{
    extern __shared__ char sm[];
    const uint32_t sb = smem_u32(sm);
    const int tid = threadIdx.x;
    const int wid = tid >> 5, lid = tid & 31;
    const int bm = blockIdx.y * 128;
    const int bn = blockIdx.x * 128;
    const int wm = (wid >> 2) * 64;
    const int wn = (wid & 3) * 32;

    const uint32_t xr     = lid & 7;
    const uint32_t a_row  = wm + (lid & 15);
    const uint32_t a_cadd = (lid >= 16) ? 4u : 0u;
    const uint32_t b_row  = wn + ((lid >> 4) << 3) + (lid & 7);
    const uint32_t b_cadd = ((lid >> 3) & 1) * 4u;

    float acc[4][4][4];
#pragma unroll
    for (int mi = 0; mi < 4; mi++)
#pragma unroll
        for (int nj = 0; nj < 4; nj++)
#pragma unroll
            for (int r = 0; r < 4; r++) acc[mi][nj][r] = 0.f;

    const int nk = K >> 5;

    auto load_tile = [&](int buf, int ks) {
        const uint32_t abuf = sb + buf * 32768;
        const uint32_t bbuf = abuf + 16384;
        const int k0 = ks * 32;
#pragma unroll
        for (int it = 0; it < 8; it++) {
            int idx = tid + it * 256;
            int c = idx & 7;
            if (idx < 1024) {
                int row = idx >> 3;
                cp16(abuf + row * 128 + ((c ^ (row & 7)) << 4),
                     A + (size_t)(bm + row) * K + k0 + c * 4);
            } else {
                int row = (idx - 1024) >> 3;
                cp16(bbuf + row * 128 + ((c ^ (row & 7)) << 4),
                     BT + (size_t)(bn + row) * K + k0 + c * 4);
            }
        }
        asm volatile("cp.async.commit_group;" ::: "memory");
    };

    load_tile(0, 0);

    for (int ks = 0; ks < nk; ks++) {
        const int buf = ks & 1;
        if (ks + 1 < nk) {
            load_tile(buf ^ 1, ks + 1);
            asm volatile("cp.async.wait_group 1;" ::: "memory");
        } else {
            asm volatile("cp.async.wait_group 0;" ::: "memory");
        }
        __syncthreads();

        const uint32_t abase = sb + buf * 32768;
        const uint32_t bbase = abase + 16384;

#pragma unroll
        for (int s = 0; s < 4; s++) {
            const int k0 = s * 8;
            uint32_t ar[4][4];
#pragma unroll
            for (int mi = 0; mi < 4; mi++) {
                uint32_t addr = abase + (a_row + mi * 16) * 128
                              + ((((k0 + a_cadd) >> 2) ^ xr) << 4);
                LDSM_X4(ar[mi][0], ar[mi][1], ar[mi][2], ar[mi][3], addr);
                CVT_TF32(ar[mi][0]); CVT_TF32(ar[mi][1]);
                CVT_TF32(ar[mi][2]); CVT_TF32(ar[mi][3]);
            }
            uint32_t br[2][4];
#pragma unroll
            for (int nb = 0; nb < 2; nb++) {
                uint32_t addr = bbase + (b_row + nb * 16) * 128
                              + ((((k0 + b_cadd) >> 2) ^ xr) << 4);
                LDSM_X4(br[nb][0], br[nb][1], br[nb][2], br[nb][3], addr);
                CVT_TF32(br[nb][0]); CVT_TF32(br[nb][1]);
                CVT_TF32(br[nb][2]); CVT_TF32(br[nb][3]);
            }
#pragma unroll
            for (int mi = 0; mi < 4; mi++)
#pragma unroll
                for (int nj = 0; nj < 4; nj++) {
                    uint32_t b0 = br[nj >> 1][(nj & 1) * 2];
                    uint32_t b1 = br[nj >> 1][(nj & 1) * 2 + 1];
                    MMA_TF32(acc[mi][nj], ar[mi][0], ar[mi][1], ar[mi][2], ar[mi][3], b0, b1);
                }
        }
        __syncthreads();
    }

    const int tq = lid >> 2;
    const int tc = (lid & 3) * 2;
#pragma unroll
    for (int mi = 0; mi < 4; mi++) {
        const int row = bm + wm + mi * 16 + tq;
#pragma unroll
        for (int nj = 0; nj < 4; nj++) {
            const int col = bn + wn + nj * 8 + tc;
            float2 bv = *(const float2*)(bias + col);
            float2 o0 = { acc[mi][nj][0] + bv.x, acc[mi][nj][1] + bv.y };
            float2 o1 = { acc[mi][nj][2] + bv.x, acc[mi][nj][3] + bv.y };
            *(float2*)(C + (size_t)row * N + col)       = o0;
            *(float2*)(C + (size_t)(row + 8) * N + col) = o1;
        }
    }
}

// ---------------------------------------------------------------------------
// RoPE (in place). X: [ROWS, nh*128].
// ---------------------------------------------------------------------------
__global__ void rope_kernel(float* __restrict__ X, int nh, float scale, int total)
{
    int idx = blockIdx.x * blockDim.x + threadIdx.x;
    if (idx >= total) return;
    const int ppr = nh * 64;
    int r   = idx / ppr;
    int rem = idx - r * ppr;
    int h = rem >> 6;
    int i = rem & 63;
    int pos = r & (SEQ - 1);

    float freq = exp2f(-((float)(2 * i) / 128.0f) * 13.287712379549449f);
    float ang = (float)pos * freq;
    float s, c;
    sincosf(ang, &s, &c);

    float* p = X + (size_t)r * (nh * HDIM) + h * HDIM + 2 * i;
    float x1 = p[0], x2 = p[1];
    p[0] = (x1 * c - x2 * s) * scale;
    p[1] = (x1 * s + x2 * c) * scale;
}

// ---------------------------------------------------------------------------
// Tensor-core flash attention (tf32 mma.sync)
// Block: 64 q-rows of one (b,h). 16 key tiles of 64. 256 threads / 8 warps.
// Smem (bytes):
//   Qs  @ 0      : 64 rows x 512B  (swizzled 16B chunks, chunk ^ (row&7))
//   Ks0 @ 32768  : 64 x 512B   Ks1 @ 65536
//   Vs0 @ 98304  : 64 x 528B (132-float padded rows, unswizzled)  Vs1 @ 132096
//   Ss  @ 165888 : 64 x 256B  (swizzled)
//   stats @ 182272: row_m[64], row_l[64], row_f[64]
// ---------------------------------------------------------------------------
#define AS_QS 0
#define AS_KS0 32768
#define AS_KS1 65536
#define AS_VS0 98304
#define AS_VS1 132096
#define AS_SS 165888
#define AS_STAT 182272
#define ATT_SMEM (AS_STAT + 768)   // 183040 bytes

__global__ __launch_bounds__(256, 1) void attn_mma_kernel()
{
    extern __shared__ char smb[];
    const uint32_t sb = smem_u32(smb);
    float* row_m = (float*)(smb + AS_STAT);
    float* row_l = row_m + 64;
    float* row_f = row_l + 64;

    const int tid = threadIdx.x;
    const int wid = tid >> 5, lid = tid & 31;
    const int b = blockIdx.x >> 4;
    const int h = blockIdx.x & 15;
    const int g = h >> 2;
    const int q0 = blockIdx.y * 64;

    const float* Qg = g_Q + (size_t)(b * SEQ + q0) * DMODEL + h * HDIM;
    const float* Kg = g_K + (size_t)(b * SEQ) * KVD + g * HDIM;
    const float* Vg = g_V + (size_t)(b * SEQ) * KVD + g * HDIM;

    const uint32_t KSo[2] = {sb + AS_KS0, sb + AS_KS1};
    const uint32_t VSo[2] = {AS_VS0, AS_VS1};

    if (tid < 64) { row_m[tid] = -INFINITY; row_l[tid] = 0.f; }

    // ---- prologue loads: Q + K0 + V0 in one cp.async group ----
#pragma unroll
    for (int it = 0; it < 8; it++) {
        int idx = tid + it * 256;
        int r = idx >> 5, c = idx & 31;
        cp16(sb + AS_QS + r * 512 + ((c ^ (r & 7)) << 4),
             Qg + (size_t)r * DMODEL + c * 4);
    }
    auto loadKV = [&](int buf, int t) {
        const float* Kt = Kg + (size_t)(t * 64) * KVD;
        const float* Vt = Vg + (size_t)(t * 64) * KVD;
#pragma unroll
        for (int it = 0; it < 8; it++) {
            int idx = tid + it * 256;
            int r = idx >> 5, c = idx & 31;
            cp16(KSo[buf] + r * 512 + ((c ^ (r & 7)) << 4),
                 Kt + (size_t)r * KVD + c * 4);
        }
#pragma unroll
        for (int it = 0; it < 8; it++) {
            int idx = tid + it * 256;
            int r = idx >> 5, c = idx & 31;
            cp16(sb + VSo[buf] + r * 528 + c * 16,
                 Vt + (size_t)r * KVD + c * 4);
        }
    };
    loadKV(0, 0);
    asm volatile("cp.async.commit_group;" ::: "memory");

    // warp geometry
    const int wmS = (wid >> 2) * 32, wnS = (wid & 3) * 16;   // S: 64x64
    const int wmP = (wid >> 2) * 32, wnP = (wid & 3) * 32;   // PV: 64x128
    const uint32_t xr     = lid & 7;
    const uint32_t a_row  = lid & 15;
    const uint32_t a_cadd = (lid >= 16) ? 4u : 0u;
    const uint32_t b_row  = ((lid >> 4) << 3) + (lid & 7);
    const uint32_t b_cadd = ((lid >> 3) & 1) * 4u;

    float oacc[2][4][4];
#pragma unroll
    for (int mi = 0; mi < 2; mi++)
#pragma unroll
        for (int nj = 0; nj < 4; nj++)
#pragma unroll
            for (int r = 0; r < 4; r++) oacc[mi][nj][r] = 0.f;

    for (int t = 0; t < SEQ / 64; t++) {
        const int buf = t & 1;
        if (t + 1 < SEQ / 64) {
            loadKV(buf ^ 1, t + 1);
            asm volatile("cp.async.commit_group;" ::: "memory");
            asm volatile("cp.async.wait_group 1;" ::: "memory");
        } else {
            asm volatile("cp.async.wait_group 0;" ::: "memory");
        }
        __syncthreads();   // tiles ready; prev PV's Ss reads done

        // ---- S = Q K^T (warp tile 32x16, K=128) ----
        float sacc[2][2][4];
#pragma unroll
        for (int mi = 0; mi < 2; mi++)
#pragma unroll
            for (int nj = 0; nj < 2; nj++)
#pragma unroll
                for (int r = 0; r < 4; r++) sacc[mi][nj][r] = 0.f;

#pragma unroll
        for (int ks = 0; ks < 16; ks++) {
            const int k0 = ks * 8;
            uint32_t ar[2][4];
#pragma unroll
            for (int mi = 0; mi < 2; mi++) {
                uint32_t addr = sb + AS_QS + (wmS + mi * 16 + a_row) * 512
                              + ((((k0 + a_cadd) >> 2) ^ xr) << 4);
                LDSM_X4(ar[mi][0], ar[mi][1], ar[mi][2], ar[mi][3], addr);
                CVT_TF32(ar[mi][0]); CVT_TF32(ar[mi][1]);
                CVT_TF32(ar[mi][2]); CVT_TF32(ar[mi][3]);
            }
            uint32_t br[4];
            {
                uint32_t addr = KSo[buf] + (wnS + b_row) * 512
                              + ((((k0 + b_cadd) >> 2) ^ xr) << 4);
                LDSM_X4(br[0], br[1], br[2], br[3], addr);
                CVT_TF32(br[0]); CVT_TF32(br[1]); CVT_TF32(br[2]); CVT_TF32(br[3]);
            }
#pragma unroll
            for (int mi = 0; mi < 2; mi++)
#pragma unroll
                for (int nj = 0; nj < 2; nj++)
                    MMA_TF32(sacc[mi][nj], ar[mi][0], ar[mi][1], ar[mi][2], ar[mi][3],
                             br[nj * 2], br[nj * 2 + 1]);
        }

        // store S (scaled) to Ss, swizzled 256B rows
#pragma unroll
        for (int mi = 0; mi < 2; mi++) {
            int r0 = wmS + mi * 16 + (lid >> 2);
#pragma unroll
            for (int nj = 0; nj < 2; nj++) {
                int col = wnS + nj * 8 + 2 * (lid & 3);
                uint32_t off = (((uint32_t)(col >> 2) ^ (r0 & 7)) << 4) + (col & 3) * 4;
                *(float2*)(smb + AS_SS + r0 * 256 + off) =
                    make_float2(sacc[mi][nj][0] * SOFTMAX_SCALE, sacc[mi][nj][1] * SOFTMAX_SCALE);
                int r1 = r0 + 8;
                uint32_t off1 = (((uint32_t)(col >> 2) ^ (r1 & 7)) << 4) + (col & 3) * 4;
                *(float2*)(smb + AS_SS + r1 * 256 + off1) =
                    make_float2(sacc[mi][nj][2] * SOFTMAX_SCALE, sacc[mi][nj][3] * SOFTMAX_SCALE);
            }
        }
        __syncthreads();

        // ---- online softmax: 4 threads per row ----
        {
            const int r = tid >> 2, seg = tid & 3;
            float4 v[4];
            uint32_t base = (uint32_t)AS_SS + r * 256;
#pragma unroll
            for (int j = 0; j < 4; j++) {
                uint32_t c = (uint32_t)(seg * 4 + j) ^ (r & 7);
                v[j] = *(const float4*)(smb + base + (c << 4));
            }
            float mx = -INFINITY;
#pragma unroll
            for (int j = 0; j < 4; j++)
                mx = fmaxf(mx, fmaxf(fmaxf(v[j].x, v[j].y), fmaxf(v[j].z, v[j].w)));
            mx = fmaxf(mx, __shfl_xor_sync(0xFFFFFFFFu, mx, 1));
            mx = fmaxf(mx, __shfl_xor_sync(0xFFFFFFFFu, mx, 2));
            float m_old = row_m[r];
            float mn = fmaxf(m_old, mx);
            float sum = 0.f;
#pragma unroll
            for (int j = 0; j < 4; j++) {
                v[j].x = __expf(v[j].x - mn);
                v[j].y = __expf(v[j].y - mn);
                v[j].z = __expf(v[j].z - mn);
                v[j].w = __expf(v[j].w - mn);
                sum += v[j].x + v[j].y + v[j].z + v[j].w;
                uint32_t c = (uint32_t)(seg * 4 + j) ^ (r & 7);
                *(float4*)(smb + base + (c << 4)) = v[j];
            }
            sum += __shfl_xor_sync(0xFFFFFFFFu, sum, 1);
            sum += __shfl_xor_sync(0xFFFFFFFFu, sum, 2);
            if (seg == 0) {
                float f = __expf(m_old - mn);
                row_m[r] = mn;
                row_f[r] = f;
                row_l[r] = row_l[r] * f + sum;
            }
        }
        __syncthreads();

        // ---- rescale O accumulator, then O += P V ----
        {
            float f0[2], f1[2];
#pragma unroll
            for (int mi = 0; mi < 2; mi++) {
                f0[mi] = row_f[wmP + mi * 16 + (lid >> 2)];
                f1[mi] = row_f[wmP + mi * 16 + (lid >> 2) + 8];
            }
#pragma unroll
            for (int mi = 0; mi < 2; mi++)
#pragma unroll
                for (int nj = 0; nj < 4; nj++) {
                    oacc[mi][nj][0] *= f0[mi]; oacc[mi][nj][1] *= f0[mi];
                    oacc[mi][nj][2] *= f1[mi]; oacc[mi][nj][3] *= f1[mi];
                }
        }
        const float* Vf = (const float*)(smb + VSo[buf]);
#pragma unroll
        for (int ks = 0; ks < 8; ks++) {
            const int k0 = ks * 8;
            uint32_t ar[2][4];
#pragma unroll
            for (int mi = 0; mi < 2; mi++) {
                uint32_t addr = sb + AS_SS + (wmP + mi * 16 + a_row) * 256
                              + ((((k0 + a_cadd) >> 2) ^ xr) << 4);
                LDSM_X4(ar[mi][0], ar[mi][1], ar[mi][2], ar[mi][3], addr);
                CVT_TF32(ar[mi][0]); CVT_TF32(ar[mi][1]);
                CVT_TF32(ar[mi][2]); CVT_TF32(ar[mi][3]);
            }
#pragma unroll
            for (int nj = 0; nj < 4; nj++) {
                int n = wnP + nj * 8 + (lid >> 2);
                uint32_t b0 = __float_as_uint(Vf[(k0 + (lid & 3)) * 132 + n]);
                uint32_t b1 = __float_as_uint(Vf[(k0 + 4 + (lid & 3)) * 132 + n]);
                CVT_TF32(b0); CVT_TF32(b1);
#pragma unroll
                for (int mi = 0; mi < 2; mi++)
                    MMA_TF32(oacc[mi][nj], ar[mi][0], ar[mi][1], ar[mi][2], ar[mi][3], b0, b1);
            }
        }
        // no trailing sync: loop-top __syncthreads covers Ss reuse
    }

    // ---- epilogue: normalize and write O ----
#pragma unroll
    for (int mi = 0; mi < 2; mi++) {
        int lr0 = wmP + mi * 16 + (lid >> 2);
        float inv0 = 1.0f / row_l[lr0];
        float inv1 = 1.0f / row_l[lr0 + 8];
        float* O0 = g_O + (size_t)(b * SEQ + q0 + lr0) * DMODEL + h * HDIM;
        float* O1 = g_O + (size_t)(b * SEQ + q0 + lr0 + 8) * DMODEL + h * HDIM;
#pragma unroll
        for (int nj = 0; nj < 4; nj++) {
            int col = wnP + nj * 8 + 2 * (lid & 3);
            *(float2*)(O0 + col) = make_float2(oacc[mi][nj][0] * inv0, oacc[mi][nj][1] * inv0);
            *(float2*)(O1 + col) = make_float2(oacc[mi][nj][2] * inv1, oacc[mi][nj][3] * inv1);
        }
    }
}

// ---------------------------------------------------------------------------
extern "C" void kernel_launch(void* const* d_in, const int* in_sizes, int n_in,
                              void* d_out, int out_size)
{
    const float* x  = (const float*)d_in[0];
    const float* Wq = (const float*)d_in[1];
    const float* bq = (const float*)d_in[2];
    const float* Wk = (const float*)d_in[3];
    const float* bk = (const float*)d_in[4];
    const float* Wv = (const float*)d_in[5];
    const float* bv = (const float*)d_in[6];
    const float* Wo = (const float*)d_in[7];
    const float* bo = (const float*)d_in[8];
    float* out = (float*)d_out;

    float *Q, *K, *V, *O, *WqT, *WkT, *WvT, *WoT;
    cudaGetSymbolAddress((void**)&Q, g_Q);
    cudaGetSymbolAddress((void**)&K, g_K);
    cudaGetSymbolAddress((void**)&V, g_V);
    cudaGetSymbolAddress((void**)&O, g_O);
    cudaGetSymbolAddress((void**)&WqT, g_WqT);
    cudaGetSymbolAddress((void**)&WkT, g_WkT);
    cudaGetSymbolAddress((void**)&WvT, g_WvT);
    cudaGetSymbolAddress((void**)&WoT, g_WoT);

    cudaFuncSetAttribute(tf32_mma_gemm,
                         cudaFuncAttributeMaxDynamicSharedMemorySize, GM_SMEM);
    cudaFuncSetAttribute(attn_mma_kernel,
                         cudaFuncAttributeMaxDynamicSharedMemorySize, ATT_SMEM);

    // Transpose weights to [N][K]
    transpose_kernel<<<dim3(DMODEL/32, DMODEL/32), dim3(32, 8)>>>(Wq, WqT, DMODEL, DMODEL);
    transpose_kernel<<<dim3(KVD/32,    DMODEL/32), dim3(32, 8)>>>(Wk, WkT, DMODEL, KVD);
    transpose_kernel<<<dim3(KVD/32,    DMODEL/32), dim3(32, 8)>>>(Wv, WvT, DMODEL, KVD);
    transpose_kernel<<<dim3(DMODEL/32, DMODEL/32), dim3(32, 8)>>>(Wo, WoT, DMODEL, DMODEL);

    // QKV projections (tf32 mma.sync)
    tf32_mma_gemm<<<dim3(DMODEL/128, ROWS/128), 256, GM_SMEM>>>(x, WqT, bq, Q, ROWS, DMODEL, DMODEL);
    tf32_mma_gemm<<<dim3(KVD/128,    ROWS/128), 256, GM_SMEM>>>(x, WkT, bk, K, ROWS, KVD, DMODEL);
    tf32_mma_gemm<<<dim3(KVD/128,    ROWS/128), 256, GM_SMEM>>>(x, WvT, bv, V, ROWS, KVD, DMODEL);

    // RoPE (Q gets head_dim^-0.5)
    {
        int totQ = ROWS * NHEADS * 64;
        int totK = ROWS * NGROUPS * 64;
        rope_kernel<<<(totQ + 255) / 256, 256>>>(Q, NHEADS, SOFTMAX_SCALE, totQ);
        rope_kernel<<<(totK + 255) / 256, 256>>>(K, NGROUPS, 1.0f, totK);
    }

    // Attention (tf32 mma flash)
    attn_mma_kernel<<<dim3(BATCH * NHEADS, SEQ / 64), 256, ATT_SMEM>>>();

    // Output projection (tf32 mma.sync)
    tf32_mma_gemm<<<dim3(DMODEL/128, ROWS/128), 256, GM_SMEM>>>(O, WoT, bo, out, ROWS, DMODEL, DMODEL);
}

// round 12
// speedup vs baseline: 7.0544x; 1.0961x over previous
#include <cuda_runtime.h>
#include <math.h>
#include <stdint.h>

#define BATCH 4
#define SEQ 1024
#define DMODEL 2048
#define KVD 512
#define NHEADS 16
#define NGROUPS 4
#define HDIM 128
#define ROWS (BATCH*SEQ)           // 4096
#define SOFTMAX_SCALE 0.08838834764831845f   // 1/sqrt(128)

// ---------------------------------------------------------------------------
// Device scratch (no allocation allowed)
// ---------------------------------------------------------------------------
__device__ float g_Q[ROWS*DMODEL];     // 32 MB
__device__ float g_K[ROWS*KVD];        // 8 MB
__device__ float g_V[ROWS*KVD];        // 8 MB
__device__ float g_O[ROWS*DMODEL];     // 32 MB (rounded-x before attention, O after)
__device__ float g_WqT[DMODEL*DMODEL]; // 16 MB  [N][K]
__device__ float g_WkT[KVD*DMODEL];    // 4 MB
__device__ float g_WvT[KVD*DMODEL];    // 4 MB
__device__ float g_WoT[DMODEL*DMODEL]; // 16 MB

// ---------------------------------------------------------------------------
// PTX helpers (sm_80-class only — NO tcgen05, harness targets bare sm_103)
// ---------------------------------------------------------------------------
__device__ __forceinline__ uint32_t smem_u32(const void* p) {
    uint32_t a;
    asm("{ .reg .u64 t; cvta.to.shared.u64 t, %1; cvt.u32.u64 %0, t; }"
        : "=r"(a) : "l"(p));
    return a;
}

__device__ __forceinline__ void cp16(uint32_t dst, const void* src) {
    asm volatile("cp.async.cg.shared.global [%0], [%1], 16;" :: "r"(dst), "l"(src));
}

__device__ __forceinline__ float f2tf32(float x) {
    uint32_t u = __float_as_uint(x);
    asm("cvt.rna.tf32.f32 %0, %0;" : "+r"(u));
    return __uint_as_float(u);
}

#define LDSM_X4(r0, r1, r2, r3, addr) \
    asm volatile("ldmatrix.sync.aligned.m8n8.x4.shared.b16 {%0,%1,%2,%3}, [%4];" \
        : "=r"(r0), "=r"(r1), "=r"(r2), "=r"(r3) : "r"(addr))

#define MMA_TF32(d, a0, a1, a2, a3, b0, b1) \
    asm volatile("mma.sync.aligned.m16n8k8.row.col.f32.tf32.tf32.f32 " \
        "{%0,%1,%2,%3}, {%4,%5,%6,%7}, {%8,%9}, {%0,%1,%2,%3};" \
        : "+f"((d)[0]), "+f"((d)[1]), "+f"((d)[2]), "+f"((d)[3]) \
        : "r"(a0), "r"(a1), "r"(a2), "r"(a3), "r"(b0), "r"(b1))

// ---------------------------------------------------------------------------
// Weight transpose: in [R][C] -> out [C][R], rounded to tf32
// ---------------------------------------------------------------------------
__global__ void transpose_kernel(const float* __restrict__ in, float* __restrict__ out,
                                 int R, int C)
{
    __shared__ float t[32][33];
    int c0 = blockIdx.x * 32, r0 = blockIdx.y * 32;
    int x = threadIdx.x, y = threadIdx.y;  // 32 x 8
#pragma unroll
    for (int i = 0; i < 32; i += 8)
        t[y + i][x] = in[(size_t)(r0 + y + i) * C + c0 + x];
    __syncthreads();
#pragma unroll
    for (int i = 0; i < 32; i += 8)
        out[(size_t)(c0 + y + i) * R + r0 + x] = f2tf32(t[x][y + i]);
}

// ---------------------------------------------------------------------------
// Round-copy: out[i] = tf32(in[i]), float4 grid-stride
// ---------------------------------------------------------------------------
__global__ void round_copy_kernel(const float4* __restrict__ in, float4* __restrict__ out,
                                  int n4)
{
    int i = blockIdx.x * blockDim.x + threadIdx.x;
    if (i >= n4) return;
    float4 v = in[i];
    v.x = f2tf32(v.x); v.y = f2tf32(v.y); v.z = f2tf32(v.z); v.w = f2tf32(v.w);
    out[i] = v;
}

// ---------------------------------------------------------------------------
// tf32 mma.sync GEMM: C[M,N] = A[M,K] @ BT[N,K]^T + bias
// A and BT must be PRE-ROUNDED to tf32 (no CVT in mainloop).
// round_out: store tf32-rounded outputs (for Q/K/V feeding further MMAs).
// ---------------------------------------------------------------------------
#define GM_SMEM 65536

__global__ __launch_bounds__(256) void tf32_mma_gemm(
    const float* __restrict__ A, const float* __restrict__ BT,
    const float* __restrict__ bias, float* __restrict__ C,
    int M, int N, int K, int round_out)
{
    extern __shared__ char sm[];
    const uint32_t sb = smem_u32(sm);
    const int tid = threadIdx.x;
    const int wid = tid >> 5, lid = tid & 31;
    const int bm = blockIdx.y * 128;
    const int bn = blockIdx.x * 128;
    const int wm = (wid >> 2) * 64;
    const int wn = (wid & 3) * 32;

    const uint32_t xr     = lid & 7;
    const uint32_t a_row  = wm + (lid & 15);
    const uint32_t a_cadd = (lid >= 16) ? 4u : 0u;
    const uint32_t b_row  = wn + ((lid >> 4) << 3) + (lid & 7);
    const uint32_t b_cadd = ((lid >> 3) & 1) * 4u;

    float acc[4][4][4];
#pragma unroll
    for (int mi = 0; mi < 4; mi++)
#pragma unroll
        for (int nj = 0; nj < 4; nj++)
#pragma unroll
            for (int r = 0; r < 4; r++) acc[mi][nj][r] = 0.f;

    const int nk = K >> 5;

    auto load_tile = [&](int buf, int ks) {
        const uint32_t abuf = sb + buf * 32768;
        const uint32_t bbuf = abuf + 16384;
        const int k0 = ks * 32;
#pragma unroll
        for (int it = 0; it < 8; it++) {
            int idx = tid + it * 256;
            int c = idx & 7;
            if (idx < 1024) {
                int row = idx >> 3;
                cp16(abuf + row * 128 + ((c ^ (row & 7)) << 4),
                     A + (size_t)(bm + row) * K + k0 + c * 4);
            } else {
                int row = (idx - 1024) >> 3;
                cp16(bbuf + row * 128 + ((c ^ (row & 7)) << 4),
                     BT + (size_t)(bn + row) * K + k0 + c * 4);
            }
        }
        asm volatile("cp.async.commit_group;" ::: "memory");
    };

    load_tile(0, 0);

    for (int ks = 0; ks < nk; ks++) {
        const int buf = ks & 1;
        if (ks + 1 < nk) {
            load_tile(buf ^ 1, ks + 1);
            asm volatile("cp.async.wait_group 1;" ::: "memory");
        } else {
            asm volatile("cp.async.wait_group 0;" ::: "memory");
        }
        __syncthreads();

        const uint32_t abase = sb + buf * 32768;
        const uint32_t bbase = abase + 16384;

#pragma unroll
        for (int s = 0; s < 4; s++) {
            const int k0 = s * 8;
            uint32_t ar[4][4];
#pragma unroll
            for (int mi = 0; mi < 4; mi++) {
                uint32_t addr = abase + (a_row + mi * 16) * 128
                              + ((((k0 + a_cadd) >> 2) ^ xr) << 4);
                LDSM_X4(ar[mi][0], ar[mi][1], ar[mi][2], ar[mi][3], addr);
            }
            uint32_t br[2][4];
#pragma unroll
            for (int nb = 0; nb < 2; nb++) {
                uint32_t addr = bbase + (b_row + nb * 16) * 128
                              + ((((k0 + b_cadd) >> 2) ^ xr) << 4);
                LDSM_X4(br[nb][0], br[nb][1], br[nb][2], br[nb][3], addr);
            }
#pragma unroll
            for (int mi = 0; mi < 4; mi++)
#pragma unroll
                for (int nj = 0; nj < 4; nj++) {
                    uint32_t b0 = br[nj >> 1][(nj & 1) * 2];
                    uint32_t b1 = br[nj >> 1][(nj & 1) * 2 + 1];
                    MMA_TF32(acc[mi][nj], ar[mi][0], ar[mi][1], ar[mi][2], ar[mi][3], b0, b1);
                }
        }
        __syncthreads();
    }

    const int tq = lid >> 2;
    const int tc = (lid & 3) * 2;
#pragma unroll
    for (int mi = 0; mi < 4; mi++) {
        const int row = bm + wm + mi * 16 + tq;
#pragma unroll
        for (int nj = 0; nj < 4; nj++) {
            const int col = bn + wn + nj * 8 + tc;
            float2 bv = *(const float2*)(bias + col);
            float2 o0 = { acc[mi][nj][0] + bv.x, acc[mi][nj][1] + bv.y };
            float2 o1 = { acc[mi][nj][2] + bv.x, acc[mi][nj][3] + bv.y };
            if (round_out) {
                o0.x = f2tf32(o0.x); o0.y = f2tf32(o0.y);
                o1.x = f2tf32(o1.x); o1.y = f2tf32(o1.y);
            }
            *(float2*)(C + (size_t)row * N + col)       = o0;
            *(float2*)(C + (size_t)(row + 8) * N + col) = o1;
        }
    }
}

// ---------------------------------------------------------------------------
// RoPE (in place), outputs rounded to tf32. X: [ROWS, nh*128].
// ---------------------------------------------------------------------------
__global__ void rope_kernel(float* __restrict__ X, int nh, float scale, int total)
{
    int idx = blockIdx.x * blockDim.x + threadIdx.x;
    if (idx >= total) return;
    const int ppr = nh * 64;
    int r   = idx / ppr;
    int rem = idx - r * ppr;
    int h = rem >> 6;
    int i = rem & 63;
    int pos = r & (SEQ - 1);

    float freq = exp2f(-((float)(2 * i) / 128.0f) * 13.287712379549449f);
    float ang = (float)pos * freq;
    float s, c;
    sincosf(ang, &s, &c);

    float* p = X + (size_t)r * (nh * HDIM) + h * HDIM + 2 * i;
    float x1 = p[0], x2 = p[1];
    p[0] = f2tf32((x1 * c - x2 * s) * scale);
    p[1] = f2tf32((x1 * s + x2 * c) * scale);
}

// ---------------------------------------------------------------------------
// Tensor-core flash attention (tf32 mma.sync; all operands pre-rounded)
// ---------------------------------------------------------------------------
#define AS_QS 0
#define AS_KS0 32768
#define AS_KS1 65536
#define AS_VS0 98304
#define AS_VS1 132096
#define AS_SS 165888
#define AS_STAT 182272
#define ATT_SMEM (AS_STAT + 768)   // 183040 bytes

__global__ __launch_bounds__(256, 1) void attn_mma_kernel()
{
    extern __shared__ char smb[];
    const uint32_t sb = smem_u32(smb);
    float* row_m = (float*)(smb + AS_STAT);
    float* row_l = row_m + 64;
    float* row_f = row_l + 64;

    const int tid = threadIdx.x;
    const int wid = tid >> 5, lid = tid & 31;
    const int b = blockIdx.x >> 4;
    const int h = blockIdx.x & 15;
    const int g = h >> 2;
    const int q0 = blockIdx.y * 64;

    const float* Qg = g_Q + (size_t)(b * SEQ + q0) * DMODEL + h * HDIM;
    const float* Kg = g_K + (size_t)(b * SEQ) * KVD + g * HDIM;
    const float* Vg = g_V + (size_t)(b * SEQ) * KVD + g * HDIM;

    const uint32_t KSo[2] = {sb + AS_KS0, sb + AS_KS1};
    const uint32_t VSo[2] = {AS_VS0, AS_VS1};

    if (tid < 64) { row_m[tid] = -INFINITY; row_l[tid] = 0.f; }

#pragma unroll
    for (int it = 0; it < 8; it++) {
        int idx = tid + it * 256;
        int r = idx >> 5, c = idx & 31;
        cp16(sb + AS_QS + r * 512 + ((c ^ (r & 7)) << 4),
             Qg + (size_t)r * DMODEL + c * 4);
    }
    auto loadKV = [&](int buf, int t) {
        const float* Kt = Kg + (size_t)(t * 64) * KVD;
        const float* Vt = Vg + (size_t)(t * 64) * KVD;
#pragma unroll
        for (int it = 0; it < 8; it++) {
            int idx = tid + it * 256;
            int r = idx >> 5, c = idx & 31;
            cp16(KSo[buf] + r * 512 + ((c ^ (r & 7)) << 4),
                 Kt + (size_t)r * KVD + c * 4);
        }
#pragma unroll
        for (int it = 0; it < 8; it++) {
            int idx = tid + it * 256;
            int r = idx >> 5, c = idx & 31;
            cp16(sb + VSo[buf] + r * 528 + c * 16,
                 Vt + (size_t)r * KVD + c * 4);
        }
    };
    loadKV(0, 0);
    asm volatile("cp.async.commit_group;" ::: "memory");

    const int wmS = (wid >> 2) * 32, wnS = (wid & 3) * 16;
    const int wmP = (wid >> 2) * 32, wnP = (wid & 3) * 32;
    const uint32_t xr     = lid & 7;
    const uint32_t a_row  = lid & 15;
    const uint32_t a_cadd = (lid >= 16) ? 4u : 0u;
    const uint32_t b_row  = ((lid >> 4) << 3) + (lid & 7);
    const uint32_t b_cadd = ((lid >> 3) & 1) * 4u;

    float oacc[2][4][4];
#pragma unroll
    for (int mi = 0; mi < 2; mi++)
#pragma unroll
        for (int nj = 0; nj < 4; nj++)
#pragma unroll
            for (int r = 0; r < 4; r++) oacc[mi][nj][r] = 0.f;

    for (int t = 0; t < SEQ / 64; t++) {
        const int buf = t & 1;
        if (t + 1 < SEQ / 64) {
            loadKV(buf ^ 1, t + 1);
            asm volatile("cp.async.commit_group;" ::: "memory");
            asm volatile("cp.async.wait_group 1;" ::: "memory");
        } else {
            asm volatile("cp.async.wait_group 0;" ::: "memory");
        }
        __syncthreads();

        // ---- S = Q K^T ----
        float sacc[2][2][4];
#pragma unroll
        for (int mi = 0; mi < 2; mi++)
#pragma unroll
            for (int nj = 0; nj < 2; nj++)
#pragma unroll
                for (int r = 0; r < 4; r++) sacc[mi][nj][r] = 0.f;

#pragma unroll
        for (int ks = 0; ks < 16; ks++) {
            const int k0 = ks * 8;
            uint32_t ar[2][4];
#pragma unroll
            for (int mi = 0; mi < 2; mi++) {
                uint32_t addr = sb + AS_QS + (wmS + mi * 16 + a_row) * 512
                              + ((((k0 + a_cadd) >> 2) ^ xr) << 4);
                LDSM_X4(ar[mi][0], ar[mi][1], ar[mi][2], ar[mi][3], addr);
            }
            uint32_t br[4];
            {
                uint32_t addr = KSo[buf] + (wnS + b_row) * 512
                              + ((((k0 + b_cadd) >> 2) ^ xr) << 4);
                LDSM_X4(br[0], br[1], br[2], br[3], addr);
            }
#pragma unroll
            for (int mi = 0; mi < 2; mi++)
#pragma unroll
                for (int nj = 0; nj < 2; nj++)
                    MMA_TF32(sacc[mi][nj], ar[mi][0], ar[mi][1], ar[mi][2], ar[mi][3],
                             br[nj * 2], br[nj * 2 + 1]);
        }

#pragma unroll
        for (int mi = 0; mi < 2; mi++) {
            int r0 = wmS + mi * 16 + (lid >> 2);
#pragma unroll
            for (int nj = 0; nj < 2; nj++) {
                int col = wnS + nj * 8 + 2 * (lid & 3);
                uint32_t off = (((uint32_t)(col >> 2) ^ (r0 & 7)) << 4) + (col & 3) * 4;
                *(float2*)(smb + AS_SS + r0 * 256 + off) =
                    make_float2(sacc[mi][nj][0] * SOFTMAX_SCALE, sacc[mi][nj][1] * SOFTMAX_SCALE);
                int r1 = r0 + 8;
                uint32_t off1 = (((uint32_t)(col >> 2) ^ (r1 & 7)) << 4) + (col & 3) * 4;
                *(float2*)(smb + AS_SS + r1 * 256 + off1) =
                    make_float2(sacc[mi][nj][2] * SOFTMAX_SCALE, sacc[mi][nj][3] * SOFTMAX_SCALE);
            }
        }
        __syncthreads();

        // ---- online softmax: 4 threads per row; P stored tf32-rounded ----
        {
            const int r = tid >> 2, seg = tid & 3;
            float4 v[4];
            uint32_t base = (uint32_t)AS_SS + r * 256;
#pragma unroll
            for (int j = 0; j < 4; j++) {
                uint32_t c = (uint32_t)(seg * 4 + j) ^ (r & 7);
                v[j] = *(const float4*)(smb + base + (c << 4));
            }
            float mx = -INFINITY;
#pragma unroll
            for (int j = 0; j < 4; j++)
                mx = fmaxf(mx, fmaxf(fmaxf(v[j].x, v[j].y), fmaxf(v[j].z, v[j].w)));
            mx = fmaxf(mx, __shfl_xor_sync(0xFFFFFFFFu, mx, 1));
            mx = fmaxf(mx, __shfl_xor_sync(0xFFFFFFFFu, mx, 2));
            float m_old = row_m[r];
            float mn = fmaxf(m_old, mx);
            float sum = 0.f;
#pragma unroll
            for (int j = 0; j < 4; j++) {
                v[j].x = __expf(v[j].x - mn);
                v[j].y = __expf(v[j].y - mn);
                v[j].z = __expf(v[j].z - mn);
                v[j].w = __expf(v[j].w - mn);
                sum += v[j].x + v[j].y + v[j].z + v[j].w;
                v[j].x = f2tf32(v[j].x); v[j].y = f2tf32(v[j].y);
                v[j].z = f2tf32(v[j].z); v[j].w = f2tf32(v[j].w);
                uint32_t c = (uint32_t)(seg * 4 + j) ^ (r & 7);
                *(float4*)(smb + base + (c << 4)) = v[j];
            }
            sum += __shfl_xor_sync(0xFFFFFFFFu, sum, 1);
            sum += __shfl_xor_sync(0xFFFFFFFFu, sum, 2);
            if (seg == 0) {
                float f = __expf(m_old - mn);
                row_m[r] = mn;
                row_f[r] = f;
                row_l[r] = row_l[r] * f + sum;
            }
        }
        __syncthreads();

        // ---- rescale O accumulator, then O += P V ----
        {
            float f0[2], f1[2];
#pragma unroll
            for (int mi = 0; mi < 2; mi++) {
                f0[mi] = row_f[wmP + mi * 16 + (lid >> 2)];
                f1[mi] = row_f[wmP + mi * 16 + (lid >> 2) + 8];
            }
#pragma unroll
            for (int mi = 0; mi < 2; mi++)
#pragma unroll
                for (int nj = 0; nj < 4; nj++) {
                    oacc[mi][nj][0] *= f0[mi]; oacc[mi][nj][1] *= f0[mi];
                    oacc[mi][nj][2] *= f1[mi]; oacc[mi][nj][3] *= f1[mi];
                }
        }
        const float* Vf = (const float*)(smb + VSo[buf]);
#pragma unroll
        for (int ks = 0; ks < 8; ks++) {
            const int k0 = ks * 8;
            uint32_t ar[2][4];
#pragma unroll
            for (int mi = 0; mi < 2; mi++) {
                uint32_t addr = sb + AS_SS + (wmP + mi * 16 + a_row) * 256
                              + ((((k0 + a_cadd) >> 2) ^ xr) << 4);
                LDSM_X4(ar[mi][0], ar[mi][1], ar[mi][2], ar[mi][3], addr);
            }
#pragma unroll
            for (int nj = 0; nj < 4; nj++) {
                int n = wnP + nj * 8 + (lid >> 2);
                uint32_t b0 = __float_as_uint(Vf[(k0 + (lid & 3)) * 132 + n]);
                uint32_t b1 = __float_as_uint(Vf[(k0 + 4 + (lid & 3)) * 132 + n]);
#pragma unroll
                for (int mi = 0; mi < 2; mi++)
                    MMA_TF32(oacc[mi][nj], ar[mi][0], ar[mi][1], ar[mi][2], ar[mi][3], b0, b1);
            }
        }
    }

    // ---- epilogue: normalize, round to tf32 (feeds O-proj A operand) ----
#pragma unroll
    for (int mi = 0; mi < 2; mi++) {
        int lr0 = wmP + mi * 16 + (lid >> 2);
        float inv0 = 1.0f / row_l[lr0];
        float inv1 = 1.0f / row_l[lr0 + 8];
        float* O0 = g_O + (size_t)(b * SEQ + q0 + lr0) * DMODEL + h * HDIM;
        float* O1 = g_O + (size_t)(b * SEQ + q0 + lr0 + 8) * DMODEL + h * HDIM;
#pragma unroll
        for (int nj = 0; nj < 4; nj++) {
            int col = wnP + nj * 8 + 2 * (lid & 3);
            *(float2*)(O0 + col) = make_float2(f2tf32(oacc[mi][nj][0] * inv0),
                                               f2tf32(oacc[mi][nj][1] * inv0));
            *(float2*)(O1 + col) = make_float2(f2tf32(oacc[mi][nj][2] * inv1),
                                               f2tf32(oacc[mi][nj][3] * inv1));
        }
    }
}

// ---------------------------------------------------------------------------
extern "C" void kernel_launch(void* const* d_in, const int* in_sizes, int n_in,
                              void* d_out, int out_size)
{
    const float* x  = (const float*)d_in[0];
    const float* Wq = (const float*)d_in[1];
    const float* bq = (const float*)d_in[2];
    const float* Wk = (const float*)d_in[3];
    const float* bk = (const float*)d_in[4];
    const float* Wv = (const float*)d_in[5];
    const float* bv = (const float*)d_in[6];
    const float* Wo = (const float*)d_in[7];
    const float* bo = (const float*)d_in[8];
    float* out = (float*)d_out;

    float *Q, *K, *V, *O, *WqT, *WkT, *WvT, *WoT;
    cudaGetSymbolAddress((void**)&Q, g_Q);
    cudaGetSymbolAddress((void**)&K, g_K);
    cudaGetSymbolAddress((void**)&V, g_V);
    cudaGetSymbolAddress((void**)&O, g_O);
    cudaGetSymbolAddress((void**)&WqT, g_WqT);
    cudaGetSymbolAddress((void**)&WkT, g_WkT);
    cudaGetSymbolAddress((void**)&WvT, g_WvT);
    cudaGetSymbolAddress((void**)&WoT, g_WoT);

    cudaFuncSetAttribute(tf32_mma_gemm,
                         cudaFuncAttributeMaxDynamicSharedMemorySize, GM_SMEM);
    cudaFuncSetAttribute(attn_mma_kernel,
                         cudaFuncAttributeMaxDynamicSharedMemorySize, ATT_SMEM);

    // Transpose weights to [N][K] (tf32-rounded)
    transpose_kernel<<<dim3(DMODEL/32, DMODEL/32), dim3(32, 8)>>>(Wq, WqT, DMODEL, DMODEL);
    transpose_kernel<<<dim3(KVD/32,    DMODEL/32), dim3(32, 8)>>>(Wk, WkT, DMODEL, KVD);
    transpose_kernel<<<dim3(KVD/32,    DMODEL/32), dim3(32, 8)>>>(Wv, WvT, DMODEL, KVD);
    transpose_kernel<<<dim3(DMODEL/32, DMODEL/32), dim3(32, 8)>>>(Wo, WoT, DMODEL, DMODEL);

    // Round x to tf32 into g_O (free until attention writes it)
    round_copy_kernel<<<(ROWS * DMODEL / 4 + 255) / 256, 256>>>(
        (const float4*)x, (float4*)O, ROWS * DMODEL / 4);

    // QKV projections (outputs tf32-rounded; Q/K re-rounded by rope anyway)
    tf32_mma_gemm<<<dim3(DMODEL/128, ROWS/128), 256, GM_SMEM>>>(O, WqT, bq, Q, ROWS, DMODEL, DMODEL, 1);
    tf32_mma_gemm<<<dim3(KVD/128,    ROWS/128), 256, GM_SMEM>>>(O, WkT, bk, K, ROWS, KVD, DMODEL, 1);
    tf32_mma_gemm<<<dim3(KVD/128,    ROWS/128), 256, GM_SMEM>>>(O, WvT, bv, V, ROWS, KVD, DMODEL, 1);

    // RoPE (Q gets head_dim^-0.5), outputs tf32-rounded
    {
        int totQ = ROWS * NHEADS * 64;
        int totK = ROWS * NGROUPS * 64;
        rope_kernel<<<(totQ + 255) / 256, 256>>>(Q, NHEADS, SOFTMAX_SCALE, totQ);
        rope_kernel<<<(totK + 255) / 256, 256>>>(K, NGROUPS, 1.0f, totK);
    }

    // Attention (tf32 mma flash); writes tf32-rounded O into g_O
    attn_mma_kernel<<<dim3(BATCH * NHEADS, SEQ / 64), 256, ATT_SMEM>>>();

    // Output projection (final fp32 output, no rounding)
    tf32_mma_gemm<<<dim3(DMODEL/128, ROWS/128), 256, GM_SMEM>>>(O, WoT, bo, out, ROWS, DMODEL, DMODEL, 0);
}

// round 13
// speedup vs baseline: 7.4612x; 1.0577x over previous
#include <cuda_runtime.h>
#include <math.h>
#include <stdint.h>

#define BATCH 4
#define SEQ 1024
#define DMODEL 2048
#define KVD 512
#define NHEADS 16
#define NGROUPS 4
#define HDIM 128
#define ROWS (BATCH*SEQ)           // 4096
#define SOFTMAX_SCALE 0.08838834764831845f   // 1/sqrt(128)

// ---------------------------------------------------------------------------
// Device scratch (no allocation allowed)
// ---------------------------------------------------------------------------
__device__ float g_Q[ROWS*DMODEL];     // 32 MB
__device__ float g_K[ROWS*KVD];        // 8 MB
__device__ float g_V[ROWS*KVD];        // 8 MB
__device__ float g_Vt[BATCH*NGROUPS*HDIM*SEQ]; // 8 MB  [b,g][dim][seq]
__device__ float g_O[ROWS*DMODEL];     // 32 MB (rounded-x before attention, O after)
__device__ float g_WqT[DMODEL*DMODEL]; // 16 MB  [N][K]
__device__ float g_WkT[KVD*DMODEL];    // 4 MB
__device__ float g_WvT[KVD*DMODEL];    // 4 MB
__device__ float g_WoT[DMODEL*DMODEL]; // 16 MB

// ---------------------------------------------------------------------------
// PTX helpers (sm_80-class only — NO tcgen05, harness targets bare sm_103)
// ---------------------------------------------------------------------------
__device__ __forceinline__ uint32_t smem_u32(const void* p) {
    uint32_t a;
    asm("{ .reg .u64 t; cvta.to.shared.u64 t, %1; cvt.u32.u64 %0, t; }"
        : "=r"(a) : "l"(p));
    return a;
}

__device__ __forceinline__ void cp16(uint32_t dst, const void* src) {
    asm volatile("cp.async.cg.shared.global [%0], [%1], 16;" :: "r"(dst), "l"(src));
}

__device__ __forceinline__ float f2tf32(float x) {
    uint32_t u = __float_as_uint(x);
    asm("cvt.rna.tf32.f32 %0, %0;" : "+r"(u));
    return __uint_as_float(u);
}

#define LDSM_X4(r0, r1, r2, r3, addr) \
    asm volatile("ldmatrix.sync.aligned.m8n8.x4.shared.b16 {%0,%1,%2,%3}, [%4];" \
        : "=r"(r0), "=r"(r1), "=r"(r2), "=r"(r3) : "r"(addr))

#define MMA_TF32(d, a0, a1, a2, a3, b0, b1) \
    asm volatile("mma.sync.aligned.m16n8k8.row.col.f32.tf32.tf32.f32 " \
        "{%0,%1,%2,%3}, {%4,%5,%6,%7}, {%8,%9}, {%0,%1,%2,%3};" \
        : "+f"((d)[0]), "+f"((d)[1]), "+f"((d)[2]), "+f"((d)[3]) \
        : "r"(a0), "r"(a1), "r"(a2), "r"(a3), "r"(b0), "r"(b1))

// ---------------------------------------------------------------------------
// Weight transpose: in [R][C] -> out [C][R], rounded to tf32
// ---------------------------------------------------------------------------
__global__ void transpose_kernel(const float* __restrict__ in, float* __restrict__ out,
                                 int R, int C)
{
    __shared__ float t[32][33];
    int c0 = blockIdx.x * 32, r0 = blockIdx.y * 32;
    int x = threadIdx.x, y = threadIdx.y;  // 32 x 8
#pragma unroll
    for (int i = 0; i < 32; i += 8)
        t[y + i][x] = in[(size_t)(r0 + y + i) * C + c0 + x];
    __syncthreads();
#pragma unroll
    for (int i = 0; i < 32; i += 8)
        out[(size_t)(c0 + y + i) * R + r0 + x] = f2tf32(t[x][y + i]);
}

// ---------------------------------------------------------------------------
// V transpose: g_V [4096][512] -> g_Vt [b,g][128 dim][1024 seq]
// (values already tf32-rounded by the V GEMM epilogue)
// ---------------------------------------------------------------------------
__global__ void v_transpose_kernel(const float* __restrict__ in, float* __restrict__ out)
{
    __shared__ float t[32][33];
    int c0 = blockIdx.x * 32, r0 = blockIdx.y * 32;
    int x = threadIdx.x, y = threadIdx.y;  // 32 x 8
#pragma unroll
    for (int i = 0; i < 32; i += 8)
        t[y + i][x] = in[(size_t)(r0 + y + i) * KVD + c0 + x];
    __syncthreads();
#pragma unroll
    for (int i = 0; i < 32; i += 8) {
        int c = c0 + y + i;        // global col: g = c>>7, d = c&127
        int r = r0 + x;            // global row: b = r>>10, s = r&1023
        out[(((size_t)(r >> 10) * NGROUPS + (c >> 7)) * HDIM + (c & 127)) * SEQ + (r & 1023)]
            = t[x][y + i];
    }
}

// ---------------------------------------------------------------------------
// Round-copy: out[i] = tf32(in[i]), float4
// ---------------------------------------------------------------------------
__global__ void round_copy_kernel(const float4* __restrict__ in, float4* __restrict__ out,
                                  int n4)
{
    int i = blockIdx.x * blockDim.x + threadIdx.x;
    if (i >= n4) return;
    float4 v = in[i];
    v.x = f2tf32(v.x); v.y = f2tf32(v.y); v.z = f2tf32(v.z); v.w = f2tf32(v.w);
    out[i] = v;
}

// ---------------------------------------------------------------------------
// tf32 mma.sync GEMM: C[M,N] = A[M,K] @ BT[N,K]^T + bias
// A and BT must be PRE-ROUNDED to tf32 (no CVT in mainloop).
// mode: 0 = plain fp32 out; 1 = tf32-rounded out; 2 = RoPE(+rope_scale)+tf32 out
// ---------------------------------------------------------------------------
#define GM_SMEM 65536

__global__ __launch_bounds__(256) void tf32_mma_gemm(
    const float* __restrict__ A, const float* __restrict__ BT,
    const float* __restrict__ bias, float* __restrict__ C,
    int M, int N, int K, int mode, float rope_scale)
{
    extern __shared__ char sm[];
    const uint32_t sb = smem_u32(sm);
    const int tid = threadIdx.x;
    const int wid = tid >> 5, lid = tid & 31;
    const int bm = blockIdx.y * 128;
    const int bn = blockIdx.x * 128;
    const int wm = (wid >> 2) * 64;
    const int wn = (wid & 3) * 32;

    const uint32_t xr     = lid & 7;
    const uint32_t a_row  = wm + (lid & 15);
    const uint32_t a_cadd = (lid >= 16) ? 4u : 0u;
    const uint32_t b_row  = wn + ((lid >> 4) << 3) + (lid & 7);
    const uint32_t b_cadd = ((lid >> 3) & 1) * 4u;

    float acc[4][4][4];
#pragma unroll
    for (int mi = 0; mi < 4; mi++)
#pragma unroll
        for (int nj = 0; nj < 4; nj++)
#pragma unroll
            for (int r = 0; r < 4; r++) acc[mi][nj][r] = 0.f;

    const int nk = K >> 5;

    auto load_tile = [&](int buf, int ks) {
        const uint32_t abuf = sb + buf * 32768;
        const uint32_t bbuf = abuf + 16384;
        const int k0 = ks * 32;
#pragma unroll
        for (int it = 0; it < 8; it++) {
            int idx = tid + it * 256;
            int c = idx & 7;
            if (idx < 1024) {
                int row = idx >> 3;
                cp16(abuf + row * 128 + ((c ^ (row & 7)) << 4),
                     A + (size_t)(bm + row) * K + k0 + c * 4);
            } else {
                int row = (idx - 1024) >> 3;
                cp16(bbuf + row * 128 + ((c ^ (row & 7)) << 4),
                     BT + (size_t)(bn + row) * K + k0 + c * 4);
            }
        }
        asm volatile("cp.async.commit_group;" ::: "memory");
    };

    load_tile(0, 0);

    for (int ks = 0; ks < nk; ks++) {
        const int buf = ks & 1;
        if (ks + 1 < nk) {
            load_tile(buf ^ 1, ks + 1);
            asm volatile("cp.async.wait_group 1;" ::: "memory");
        } else {
            asm volatile("cp.async.wait_group 0;" ::: "memory");
        }
        __syncthreads();

        const uint32_t abase = sb + buf * 32768;
        const uint32_t bbase = abase + 16384;

#pragma unroll
        for (int s = 0; s < 4; s++) {
            const int k0 = s * 8;
            uint32_t ar[4][4];
#pragma unroll
            for (int mi = 0; mi < 4; mi++) {
                uint32_t addr = abase + (a_row + mi * 16) * 128
                              + ((((k0 + a_cadd) >> 2) ^ xr) << 4);
                LDSM_X4(ar[mi][0], ar[mi][1], ar[mi][2], ar[mi][3], addr);
            }
            uint32_t br[2][4];
#pragma unroll
            for (int nb = 0; nb < 2; nb++) {
                uint32_t addr = bbase + (b_row + nb * 16) * 128
                              + ((((k0 + b_cadd) >> 2) ^ xr) << 4);
                LDSM_X4(br[nb][0], br[nb][1], br[nb][2], br[nb][3], addr);
            }
#pragma unroll
            for (int mi = 0; mi < 4; mi++)
#pragma unroll
                for (int nj = 0; nj < 4; nj++) {
                    uint32_t b0 = br[nj >> 1][(nj & 1) * 2];
                    uint32_t b1 = br[nj >> 1][(nj & 1) * 2 + 1];
                    MMA_TF32(acc[mi][nj], ar[mi][0], ar[mi][1], ar[mi][2], ar[mi][3], b0, b1);
                }
        }
        __syncthreads();
    }

    const int tq = lid >> 2;
    const int tc = (lid & 3) * 2;
#pragma unroll
    for (int mi = 0; mi < 4; mi++) {
        const int row = bm + wm + mi * 16 + tq;
#pragma unroll
        for (int nj = 0; nj < 4; nj++) {
            const int col = bn + wn + nj * 8 + tc;   // always even
            float2 bv = *(const float2*)(bias + col);
            float2 o0 = { acc[mi][nj][0] + bv.x, acc[mi][nj][1] + bv.y };
            float2 o1 = { acc[mi][nj][2] + bv.x, acc[mi][nj][3] + bv.y };
            if (mode == 2) {
                // RoPE on adjacent pair (col, col+1): i = (col%128)/2, pos = row%SEQ
                int i = (col & 127) >> 1;
                float freq = exp2f(-((float)(2 * i) / 128.0f) * 13.287712379549449f);
                float s0, c0, s1, c1;
                sincosf((float)(row & (SEQ - 1)) * freq, &s0, &c0);
                sincosf((float)((row + 8) & (SEQ - 1)) * freq, &s1, &c1);
                float x0 = o0.x, y0 = o0.y, x1 = o1.x, y1 = o1.y;
                o0.x = (x0 * c0 - y0 * s0) * rope_scale;
                o0.y = (x0 * s0 + y0 * c0) * rope_scale;
                o1.x = (x1 * c1 - y1 * s1) * rope_scale;
                o1.y = (x1 * s1 + y1 * c1) * rope_scale;
            }
            if (mode != 0) {
                o0.x = f2tf32(o0.x); o0.y = f2tf32(o0.y);
                o1.x = f2tf32(o1.x); o1.y = f2tf32(o1.y);
            }
            *(float2*)(C + (size_t)row * N + col)       = o0;
            *(float2*)(C + (size_t)(row + 8) * N + col) = o1;
        }
    }
}

// ---------------------------------------------------------------------------
// Tensor-core flash attention (tf32 mma.sync; all operands pre-rounded)
// Smem: Qs 64x512B @0; Ks 64x512B x2; Vt 128x256B x2 ([dim][keys]); Ss 64x256B
// ---------------------------------------------------------------------------
#define AS_QS 0
#define AS_KS0 32768
#define AS_KS1 65536
#define AS_VS0 98304
#define AS_VS1 131072
#define AS_SS 163840
#define AS_STAT 180224
#define ATT_SMEM (AS_STAT + 768)   // 180992 bytes

__global__ __launch_bounds__(256, 1) void attn_mma_kernel()
{
    extern __shared__ char smb[];
    const uint32_t sb = smem_u32(smb);
    float* row_m = (float*)(smb + AS_STAT);
    float* row_l = row_m + 64;
    float* row_f = row_l + 64;

    const int tid = threadIdx.x;
    const int wid = tid >> 5, lid = tid & 31;
    const int b = blockIdx.x >> 4;
    const int h = blockIdx.x & 15;
    const int g = h >> 2;
    const int q0 = blockIdx.y * 64;

    const float* Qg  = g_Q + (size_t)(b * SEQ + q0) * DMODEL + h * HDIM;
    const float* Kg  = g_K + (size_t)(b * SEQ) * KVD + g * HDIM;
    const float* Vtg = g_Vt + ((size_t)(b * NGROUPS + g)) * HDIM * SEQ;

    const uint32_t KSo[2] = {sb + AS_KS0, sb + AS_KS1};
    const uint32_t VSo[2] = {sb + AS_VS0, sb + AS_VS1};

    if (tid < 64) { row_m[tid] = -INFINITY; row_l[tid] = 0.f; }

#pragma unroll
    for (int it = 0; it < 8; it++) {
        int idx = tid + it * 256;
        int r = idx >> 5, c = idx & 31;
        cp16(sb + AS_QS + r * 512 + ((c ^ (r & 7)) << 4),
             Qg + (size_t)r * DMODEL + c * 4);
    }
    auto loadKV = [&](int buf, int t) {
        const float* Kt = Kg + (size_t)(t * 64) * KVD;
        const float* Vt = Vtg + t * 64;
#pragma unroll
        for (int it = 0; it < 8; it++) {
            int idx = tid + it * 256;
            int r = idx >> 5, c = idx & 31;
            cp16(KSo[buf] + r * 512 + ((c ^ (r & 7)) << 4),
                 Kt + (size_t)r * KVD + c * 4);
        }
        // Vt tile: 128 dim-rows x 64 keys (256B rows, swizzled 16B chunks)
#pragma unroll
        for (int it = 0; it < 8; it++) {
            int idx = tid + it * 256;
            int r = idx >> 4, c = idx & 15;
            cp16(VSo[buf] + r * 256 + (((uint32_t)c ^ (r & 7)) << 4),
                 Vt + (size_t)r * SEQ + c * 4);
        }
    };
    loadKV(0, 0);
    asm volatile("cp.async.commit_group;" ::: "memory");

    const int wmS = (wid >> 2) * 32, wnS = (wid & 3) * 16;
    const int wmP = (wid >> 2) * 32, wnP = (wid & 3) * 32;
    const uint32_t xr     = lid & 7;
    const uint32_t a_row  = lid & 15;
    const uint32_t a_cadd = (lid >= 16) ? 4u : 0u;
    const uint32_t b_row  = ((lid >> 4) << 3) + (lid & 7);
    const uint32_t b_cadd = ((lid >> 3) & 1) * 4u;

    float oacc[2][4][4];
#pragma unroll
    for (int mi = 0; mi < 2; mi++)
#pragma unroll
        for (int nj = 0; nj < 4; nj++)
#pragma unroll
            for (int r = 0; r < 4; r++) oacc[mi][nj][r] = 0.f;

    for (int t = 0; t < SEQ / 64; t++) {
        const int buf = t & 1;
        if (t + 1 < SEQ / 64) {
            loadKV(buf ^ 1, t + 1);
            asm volatile("cp.async.commit_group;" ::: "memory");
            asm volatile("cp.async.wait_group 1;" ::: "memory");
        } else {
            asm volatile("cp.async.wait_group 0;" ::: "memory");
        }
        __syncthreads();

        // ---- S = Q K^T ----
        float sacc[2][2][4];
#pragma unroll
        for (int mi = 0; mi < 2; mi++)
#pragma unroll
            for (int nj = 0; nj < 2; nj++)
#pragma unroll
                for (int r = 0; r < 4; r++) sacc[mi][nj][r] = 0.f;

#pragma unroll
        for (int ks = 0; ks < 16; ks++) {
            const int k0 = ks * 8;
            uint32_t ar[2][4];
#pragma unroll
            for (int mi = 0; mi < 2; mi++) {
                uint32_t addr = sb + AS_QS + (wmS + mi * 16 + a_row) * 512
                              + ((((k0 + a_cadd) >> 2) ^ xr) << 4);
                LDSM_X4(ar[mi][0], ar[mi][1], ar[mi][2], ar[mi][3], addr);
            }
            uint32_t br[4];
            {
                uint32_t addr = KSo[buf] + (wnS + b_row) * 512
                              + ((((k0 + b_cadd) >> 2) ^ xr) << 4);
                LDSM_X4(br[0], br[1], br[2], br[3], addr);
            }
#pragma unroll
            for (int mi = 0; mi < 2; mi++)
#pragma unroll
                for (int nj = 0; nj < 2; nj++)
                    MMA_TF32(sacc[mi][nj], ar[mi][0], ar[mi][1], ar[mi][2], ar[mi][3],
                             br[nj * 2], br[nj * 2 + 1]);
        }

#pragma unroll
        for (int mi = 0; mi < 2; mi++) {
            int r0 = wmS + mi * 16 + (lid >> 2);
#pragma unroll
            for (int nj = 0; nj < 2; nj++) {
                int col = wnS + nj * 8 + 2 * (lid & 3);
                uint32_t off = (((uint32_t)(col >> 2) ^ (r0 & 7)) << 4) + (col & 3) * 4;
                *(float2*)(smb + AS_SS + r0 * 256 + off) =
                    make_float2(sacc[mi][nj][0] * SOFTMAX_SCALE, sacc[mi][nj][1] * SOFTMAX_SCALE);
                int r1 = r0 + 8;
                uint32_t off1 = (((uint32_t)(col >> 2) ^ (r1 & 7)) << 4) + (col & 3) * 4;
                *(float2*)(smb + AS_SS + r1 * 256 + off1) =
                    make_float2(sacc[mi][nj][2] * SOFTMAX_SCALE, sacc[mi][nj][3] * SOFTMAX_SCALE);
            }
        }
        __syncthreads();

        // ---- online softmax: 4 threads per row; P stored tf32-rounded ----
        {
            const int r = tid >> 2, seg = tid & 3;
            float4 v[4];
            uint32_t base = (uint32_t)AS_SS + r * 256;
#pragma unroll
            for (int j = 0; j < 4; j++) {
                uint32_t c = (uint32_t)(seg * 4 + j) ^ (r & 7);
                v[j] = *(const float4*)(smb + base + (c << 4));
            }
            float mx = -INFINITY;
#pragma unroll
            for (int j = 0; j < 4; j++)
                mx = fmaxf(mx, fmaxf(fmaxf(v[j].x, v[j].y), fmaxf(v[j].z, v[j].w)));
            mx = fmaxf(mx, __shfl_xor_sync(0xFFFFFFFFu, mx, 1));
            mx = fmaxf(mx, __shfl_xor_sync(0xFFFFFFFFu, mx, 2));
            float m_old = row_m[r];
            float mn = fmaxf(m_old, mx);
            float sum = 0.f;
#pragma unroll
            for (int j = 0; j < 4; j++) {
                v[j].x = __expf(v[j].x - mn);
                v[j].y = __expf(v[j].y - mn);
                v[j].z = __expf(v[j].z - mn);
                v[j].w = __expf(v[j].w - mn);
                sum += v[j].x + v[j].y + v[j].z + v[j].w;
                v[j].x = f2tf32(v[j].x); v[j].y = f2tf32(v[j].y);
                v[j].z = f2tf32(v[j].z); v[j].w = f2tf32(v[j].w);
                uint32_t c = (uint32_t)(seg * 4 + j) ^ (r & 7);
                *(float4*)(smb + base + (c << 4)) = v[j];
            }
            sum += __shfl_xor_sync(0xFFFFFFFFu, sum, 1);
            sum += __shfl_xor_sync(0xFFFFFFFFu, sum, 2);
            if (seg == 0) {
                float f = __expf(m_old - mn);
                row_m[r] = mn;
                row_f[r] = f;
                row_l[r] = row_l[r] * f + sum;
            }
        }
        __syncthreads();

        // ---- rescale O accumulator, then O += P V (B via ldmatrix from Vt) ----
        {
            float f0[2], f1[2];
#pragma unroll
            for (int mi = 0; mi < 2; mi++) {
                f0[mi] = row_f[wmP + mi * 16 + (lid >> 2)];
                f1[mi] = row_f[wmP + mi * 16 + (lid >> 2) + 8];
            }
#pragma unroll
            for (int mi = 0; mi < 2; mi++)
#pragma unroll
                for (int nj = 0; nj < 4; nj++) {
                    oacc[mi][nj][0] *= f0[mi]; oacc[mi][nj][1] *= f0[mi];
                    oacc[mi][nj][2] *= f1[mi]; oacc[mi][nj][3] *= f1[mi];
                }
        }
#pragma unroll
        for (int ks = 0; ks < 8; ks++) {
            const int k0 = ks * 8;
            uint32_t ar[2][4];
#pragma unroll
            for (int mi = 0; mi < 2; mi++) {
                uint32_t addr = sb + AS_SS + (wmP + mi * 16 + a_row) * 256
                              + ((((k0 + a_cadd) >> 2) ^ xr) << 4);
                LDSM_X4(ar[mi][0], ar[mi][1], ar[mi][2], ar[mi][3], addr);
            }
            uint32_t br[2][4];
#pragma unroll
            for (int nb = 0; nb < 2; nb++) {
                uint32_t addr = VSo[buf] + (wnP + nb * 16 + b_row) * 256
                              + ((((k0 + b_cadd) >> 2) ^ xr) << 4);
                LDSM_X4(br[nb][0], br[nb][1], br[nb][2], br[nb][3], addr);
            }
#pragma unroll
            for (int mi = 0; mi < 2; mi++)
#pragma unroll
                for (int nj = 0; nj < 4; nj++)
                    MMA_TF32(oacc[mi][nj], ar[mi][0], ar[mi][1], ar[mi][2], ar[mi][3],
                             br[nj >> 1][(nj & 1) * 2], br[nj >> 1][(nj & 1) * 2 + 1]);
        }
    }

    // ---- epilogue: normalize, round to tf32 (feeds O-proj A operand) ----
#pragma unroll
    for (int mi = 0; mi < 2; mi++) {
        int lr0 = wmP + mi * 16 + (lid >> 2);
        float inv0 = 1.0f / row_l[lr0];
        float inv1 = 1.0f / row_l[lr0 + 8];
        float* O0 = g_O + (size_t)(b * SEQ + q0 + lr0) * DMODEL + h * HDIM;
        float* O1 = g_O + (size_t)(b * SEQ + q0 + lr0 + 8) * DMODEL + h * HDIM;
#pragma unroll
        for (int nj = 0; nj < 4; nj++) {
            int col = wnP + nj * 8 + 2 * (lid & 3);
            *(float2*)(O0 + col) = make_float2(f2tf32(oacc[mi][nj][0] * inv0),
                                               f2tf32(oacc[mi][nj][1] * inv0));
            *(float2*)(O1 + col) = make_float2(f2tf32(oacc[mi][nj][2] * inv1),
                                               f2tf32(oacc[mi][nj][3] * inv1));
        }
    }
}

// ---------------------------------------------------------------------------
extern "C" void kernel_launch(void* const* d_in, const int* in_sizes, int n_in,
                              void* d_out, int out_size)
{
    const float* x  = (const float*)d_in[0];
    const float* Wq = (const float*)d_in[1];
    const float* bq = (const float*)d_in[2];
    const float* Wk = (const float*)d_in[3];
    const float* bk = (const float*)d_in[4];
    const float* Wv = (const float*)d_in[5];
    const float* bv = (const float*)d_in[6];
    const float* Wo = (const float*)d_in[7];
    const float* bo = (const float*)d_in[8];
    float* out = (float*)d_out;

    float *Q, *K, *V, *Vt, *O, *WqT, *WkT, *WvT, *WoT;
    cudaGetSymbolAddress((void**)&Q, g_Q);
    cudaGetSymbolAddress((void**)&K, g_K);
    cudaGetSymbolAddress((void**)&V, g_V);
    cudaGetSymbolAddress((void**)&Vt, g_Vt);
    cudaGetSymbolAddress((void**)&O, g_O);
    cudaGetSymbolAddress((void**)&WqT, g_WqT);
    cudaGetSymbolAddress((void**)&WkT, g_WkT);
    cudaGetSymbolAddress((void**)&WvT, g_WvT);
    cudaGetSymbolAddress((void**)&WoT, g_WoT);

    cudaFuncSetAttribute(tf32_mma_gemm,
                         cudaFuncAttributeMaxDynamicSharedMemorySize, GM_SMEM);
    cudaFuncSetAttribute(attn_mma_kernel,
                         cudaFuncAttributeMaxDynamicSharedMemorySize, ATT_SMEM);

    // Transpose weights to [N][K] (tf32-rounded)
    transpose_kernel<<<dim3(DMODEL/32, DMODEL/32), dim3(32, 8)>>>(Wq, WqT, DMODEL, DMODEL);
    transpose_kernel<<<dim3(KVD/32,    DMODEL/32), dim3(32, 8)>>>(Wk, WkT, DMODEL, KVD);
    transpose_kernel<<<dim3(KVD/32,    DMODEL/32), dim3(32, 8)>>>(Wv, WvT, DMODEL, KVD);
    transpose_kernel<<<dim3(DMODEL/32, DMODEL/32), dim3(32, 8)>>>(Wo, WoT, DMODEL, DMODEL);

    // Round x to tf32 into g_O (free until attention writes it)
    round_copy_kernel<<<(ROWS * DMODEL / 4 + 255) / 256, 256>>>(
        (const float4*)x, (float4*)O, ROWS * DMODEL / 4);

    // Q/K projections with fused RoPE (+round); V projection (+round)
    tf32_mma_gemm<<<dim3(DMODEL/128, ROWS/128), 256, GM_SMEM>>>(O, WqT, bq, Q, ROWS, DMODEL, DMODEL, 2, SOFTMAX_SCALE);
    tf32_mma_gemm<<<dim3(KVD/128,    ROWS/128), 256, GM_SMEM>>>(O, WkT, bk, K, ROWS, KVD, DMODEL, 2, 1.0f);
    tf32_mma_gemm<<<dim3(KVD/128,    ROWS/128), 256, GM_SMEM>>>(O, WvT, bv, V, ROWS, KVD, DMODEL, 1, 1.0f);

    // Transpose V per (b,g) to [dim][seq] for ldmatrix-friendly PV
    v_transpose_kernel<<<dim3(KVD/32, ROWS/32), dim3(32, 8)>>>(V, Vt);

    // Attention (tf32 mma flash); writes tf32-rounded O into g_O
    attn_mma_kernel<<<dim3(BATCH * NHEADS, SEQ / 64), 256, ATT_SMEM>>>();

    // Output projection (final fp32 output, no rounding)
    tf32_mma_gemm<<<dim3(DMODEL/128, ROWS/128), 256, GM_SMEM>>>(O, WoT, bo, out, ROWS, DMODEL, DMODEL, 0, 1.0f);
}

// round 14
// speedup vs baseline: 7.6356x; 1.0234x over previous
#include <cuda_runtime.h>
#include <math.h>
#include <stdint.h>

#define BATCH 4
#define SEQ 1024
#define DMODEL 2048
#define KVD 512
#define NHEADS 16
#define NGROUPS 4
#define HDIM 128
#define ROWS (BATCH*SEQ)           // 4096
#define SOFTMAX_SCALE 0.08838834764831845f   // 1/sqrt(128)

// ---------------------------------------------------------------------------
// Device scratch (no allocation allowed)
// ---------------------------------------------------------------------------
__device__ float g_Q[ROWS*DMODEL];     // 32 MB
__device__ float g_K[ROWS*KVD];        // 8 MB
__device__ float g_V[ROWS*KVD];        // 8 MB
__device__ float g_Vt[BATCH*NGROUPS*HDIM*SEQ]; // 8 MB  [b,g][dim][seq]
__device__ float g_O[ROWS*DMODEL];     // 32 MB (rounded-x before attention, O after)
__device__ float g_WqT[DMODEL*DMODEL]; // 16 MB  [N][K]
__device__ float g_WkT[KVD*DMODEL];    // 4 MB
__device__ float g_WvT[KVD*DMODEL];    // 4 MB
__device__ float g_WoT[DMODEL*DMODEL]; // 16 MB

// ---------------------------------------------------------------------------
// PTX helpers (sm_80-class only — NO tcgen05, harness targets bare sm_103)
// ---------------------------------------------------------------------------
__device__ __forceinline__ uint32_t smem_u32(const void* p) {
    uint32_t a;
    asm("{ .reg .u64 t; cvta.to.shared.u64 t, %1; cvt.u32.u64 %0, t; }"
        : "=r"(a) : "l"(p));
    return a;
}

__device__ __forceinline__ void cp16(uint32_t dst, const void* src) {
    asm volatile("cp.async.cg.shared.global [%0], [%1], 16;" :: "r"(dst), "l"(src));
}

__device__ __forceinline__ float f2tf32(float x) {
    uint32_t u = __float_as_uint(x);
    asm("cvt.rna.tf32.f32 %0, %0;" : "+r"(u));
    return __uint_as_float(u);
}

#define LDSM_X4(r0, r1, r2, r3, addr) \
    asm volatile("ldmatrix.sync.aligned.m8n8.x4.shared.b16 {%0,%1,%2,%3}, [%4];" \
        : "=r"(r0), "=r"(r1), "=r"(r2), "=r"(r3) : "r"(addr))

#define MMA_TF32(d, a0, a1, a2, a3, b0, b1) \
    asm volatile("mma.sync.aligned.m16n8k8.row.col.f32.tf32.tf32.f32 " \
        "{%0,%1,%2,%3}, {%4,%5,%6,%7}, {%8,%9}, {%0,%1,%2,%3};" \
        : "+f"((d)[0]), "+f"((d)[1]), "+f"((d)[2]), "+f"((d)[3]) \
        : "r"(a0), "r"(a1), "r"(a2), "r"(a3), "r"(b0), "r"(b1))

// ---------------------------------------------------------------------------
// Weight transpose: in [R][C] -> out [C][R], rounded to tf32
// ---------------------------------------------------------------------------
__global__ void transpose_kernel(const float* __restrict__ in, float* __restrict__ out,
                                 int R, int C)
{
    __shared__ float t[32][33];
    int c0 = blockIdx.x * 32, r0 = blockIdx.y * 32;
    int x = threadIdx.x, y = threadIdx.y;  // 32 x 8
#pragma unroll
    for (int i = 0; i < 32; i += 8)
        t[y + i][x] = in[(size_t)(r0 + y + i) * C + c0 + x];
    __syncthreads();
#pragma unroll
    for (int i = 0; i < 32; i += 8)
        out[(size_t)(c0 + y + i) * R + r0 + x] = f2tf32(t[x][y + i]);
}

// ---------------------------------------------------------------------------
// V transpose: g_V [4096][512] -> g_Vt [b,g][128 dim][1024 seq]
// ---------------------------------------------------------------------------
__global__ void v_transpose_kernel(const float* __restrict__ in, float* __restrict__ out)
{
    __shared__ float t[32][33];
    int c0 = blockIdx.x * 32, r0 = blockIdx.y * 32;
    int x = threadIdx.x, y = threadIdx.y;  // 32 x 8
#pragma unroll
    for (int i = 0; i < 32; i += 8)
        t[y + i][x] = in[(size_t)(r0 + y + i) * KVD + c0 + x];
    __syncthreads();
#pragma unroll
    for (int i = 0; i < 32; i += 8) {
        int c = c0 + y + i;        // global col: g = c>>7, d = c&127
        int r = r0 + x;            // global row: b = r>>10, s = r&1023
        out[(((size_t)(r >> 10) * NGROUPS + (c >> 7)) * HDIM + (c & 127)) * SEQ + (r & 1023)]
            = t[x][y + i];
    }
}

// ---------------------------------------------------------------------------
// Round-copy: out[i] = tf32(in[i]), float4
// ---------------------------------------------------------------------------
__global__ void round_copy_kernel(const float4* __restrict__ in, float4* __restrict__ out,
                                  int n4)
{
    int i = blockIdx.x * blockDim.x + threadIdx.x;
    if (i >= n4) return;
    float4 v = in[i];
    v.x = f2tf32(v.x); v.y = f2tf32(v.y); v.z = f2tf32(v.z); v.w = f2tf32(v.w);
    out[i] = v;
}

// ---------------------------------------------------------------------------
// tf32 mma.sync GEMM: C[M,N] = A[M,K] @ BT[N,K]^T + bias
// mode: 0 = plain fp32 out; 1 = tf32-rounded out; 2 = RoPE(+rope_scale)+tf32 out
// ---------------------------------------------------------------------------
#define GM_SMEM 65536

__global__ __launch_bounds__(256) void tf32_mma_gemm(
    const float* __restrict__ A, const float* __restrict__ BT,
    const float* __restrict__ bias, float* __restrict__ C,
    int M, int N, int K, int mode, float rope_scale)
{
    extern __shared__ char sm[];
    const uint32_t sb = smem_u32(sm);
    const int tid = threadIdx.x;
    const int wid = tid >> 5, lid = tid & 31;
    const int bm = blockIdx.y * 128;
    const int bn = blockIdx.x * 128;
    const int wm = (wid >> 2) * 64;
    const int wn = (wid & 3) * 32;

    const uint32_t xr     = lid & 7;
    const uint32_t a_row  = wm + (lid & 15);
    const uint32_t a_cadd = (lid >= 16) ? 4u : 0u;
    const uint32_t b_row  = wn + ((lid >> 4) << 3) + (lid & 7);
    const uint32_t b_cadd = ((lid >> 3) & 1) * 4u;

    float acc[4][4][4];
#pragma unroll
    for (int mi = 0; mi < 4; mi++)
#pragma unroll
        for (int nj = 0; nj < 4; nj++)
#pragma unroll
            for (int r = 0; r < 4; r++) acc[mi][nj][r] = 0.f;

    const int nk = K >> 5;

    auto load_tile = [&](int buf, int ks) {
        const uint32_t abuf = sb + buf * 32768;
        const uint32_t bbuf = abuf + 16384;
        const int k0 = ks * 32;
#pragma unroll
        for (int it = 0; it < 8; it++) {
            int idx = tid + it * 256;
            int c = idx & 7;
            if (idx < 1024) {
                int row = idx >> 3;
                cp16(abuf + row * 128 + ((c ^ (row & 7)) << 4),
                     A + (size_t)(bm + row) * K + k0 + c * 4);
            } else {
                int row = (idx - 1024) >> 3;
                cp16(bbuf + row * 128 + ((c ^ (row & 7)) << 4),
                     BT + (size_t)(bn + row) * K + k0 + c * 4);
            }
        }
        asm volatile("cp.async.commit_group;" ::: "memory");
    };

    load_tile(0, 0);

    for (int ks = 0; ks < nk; ks++) {
        const int buf = ks & 1;
        if (ks + 1 < nk) {
            load_tile(buf ^ 1, ks + 1);
            asm volatile("cp.async.wait_group 1;" ::: "memory");
        } else {
            asm volatile("cp.async.wait_group 0;" ::: "memory");
        }
        __syncthreads();

        const uint32_t abase = sb + buf * 32768;
        const uint32_t bbase = abase + 16384;

#pragma unroll
        for (int s = 0; s < 4; s++) {
            const int k0 = s * 8;
            uint32_t ar[4][4];
#pragma unroll
            for (int mi = 0; mi < 4; mi++) {
                uint32_t addr = abase + (a_row + mi * 16) * 128
                              + ((((k0 + a_cadd) >> 2) ^ xr) << 4);
                LDSM_X4(ar[mi][0], ar[mi][1], ar[mi][2], ar[mi][3], addr);
            }
            uint32_t br[2][4];
#pragma unroll
            for (int nb = 0; nb < 2; nb++) {
                uint32_t addr = bbase + (b_row + nb * 16) * 128
                              + ((((k0 + b_cadd) >> 2) ^ xr) << 4);
                LDSM_X4(br[nb][0], br[nb][1], br[nb][2], br[nb][3], addr);
            }
#pragma unroll
            for (int mi = 0; mi < 4; mi++)
#pragma unroll
                for (int nj = 0; nj < 4; nj++) {
                    uint32_t b0 = br[nj >> 1][(nj & 1) * 2];
                    uint32_t b1 = br[nj >> 1][(nj & 1) * 2 + 1];
                    MMA_TF32(acc[mi][nj], ar[mi][0], ar[mi][1], ar[mi][2], ar[mi][3], b0, b1);
                }
        }
        __syncthreads();
    }

    const int tq = lid >> 2;
    const int tc = (lid & 3) * 2;
#pragma unroll
    for (int mi = 0; mi < 4; mi++) {
        const int row = bm + wm + mi * 16 + tq;
#pragma unroll
        for (int nj = 0; nj < 4; nj++) {
            const int col = bn + wn + nj * 8 + tc;   // always even
            float2 bv = *(const float2*)(bias + col);
            float2 o0 = { acc[mi][nj][0] + bv.x, acc[mi][nj][1] + bv.y };
            float2 o1 = { acc[mi][nj][2] + bv.x, acc[mi][nj][3] + bv.y };
            if (mode == 2) {
                int i = (col & 127) >> 1;
                float freq = exp2f(-((float)(2 * i) / 128.0f) * 13.287712379549449f);
                float s0, c0, s1, c1;
                sincosf((float)(row & (SEQ - 1)) * freq, &s0, &c0);
                sincosf((float)((row + 8) & (SEQ - 1)) * freq, &s1, &c1);
                float x0 = o0.x, y0 = o0.y, x1 = o1.x, y1 = o1.y;
                o0.x = (x0 * c0 - y0 * s0) * rope_scale;
                o0.y = (x0 * s0 + y0 * c0) * rope_scale;
                o1.x = (x1 * c1 - y1 * s1) * rope_scale;
                o1.y = (x1 * s1 + y1 * c1) * rope_scale;
            }
            if (mode != 0) {
                o0.x = f2tf32(o0.x); o0.y = f2tf32(o0.y);
                o1.x = f2tf32(o1.x); o1.y = f2tf32(o1.y);
            }
            *(float2*)(C + (size_t)row * N + col)       = o0;
            *(float2*)(C + (size_t)(row + 8) * N + col) = o1;
        }
    }
}

// ---------------------------------------------------------------------------
// Tensor-core flash attention, BM=128 q-rows per CTA (tf32 mma.sync)
// Smem: Qs 128x512B @0; Ks 64x512B x2; Vt 128x256B x2; Ss 128x256B; stats
// Warps: 4(M) x 2(N). S warp-tile 32x32; PV warp-tile 32x64.
// ---------------------------------------------------------------------------
#define AS_QS 0
#define AS_KS0 65536
#define AS_KS1 98304
#define AS_VS0 131072
#define AS_VS1 163840
#define AS_SS 196608
#define AS_STAT 229376
#define ATT_SMEM (AS_STAT + 1536)   // 230912 bytes

__global__ __launch_bounds__(256, 1) void attn_mma_kernel()
{
    extern __shared__ char smb[];
    const uint32_t sb = smem_u32(smb);
    float* row_m = (float*)(smb + AS_STAT);
    float* row_l = row_m + 128;
    float* row_f = row_l + 128;

    const int tid = threadIdx.x;
    const int wid = tid >> 5, lid = tid & 31;
    const int b = blockIdx.x >> 4;
    const int h = blockIdx.x & 15;
    const int g = h >> 2;
    const int q0 = blockIdx.y * 128;

    const float* Qg  = g_Q + (size_t)(b * SEQ + q0) * DMODEL + h * HDIM;
    const float* Kg  = g_K + (size_t)(b * SEQ) * KVD + g * HDIM;
    const float* Vtg = g_Vt + ((size_t)(b * NGROUPS + g)) * HDIM * SEQ;

    const uint32_t KSo[2] = {sb + AS_KS0, sb + AS_KS1};
    const uint32_t VSo[2] = {sb + AS_VS0, sb + AS_VS1};

    if (tid < 128) { row_m[tid] = -INFINITY; row_l[tid] = 0.f; }

    // Q: 128 rows x 512B swizzled
#pragma unroll
    for (int it = 0; it < 16; it++) {
        int idx = tid + it * 256;
        int r = idx >> 5, c = idx & 31;
        cp16(sb + AS_QS + r * 512 + ((c ^ (r & 7)) << 4),
             Qg + (size_t)r * DMODEL + c * 4);
    }
    auto loadKV = [&](int buf, int t) {
        const float* Kt = Kg + (size_t)(t * 64) * KVD;
        const float* Vt = Vtg + t * 64;
#pragma unroll
        for (int it = 0; it < 8; it++) {
            int idx = tid + it * 256;
            int r = idx >> 5, c = idx & 31;
            cp16(KSo[buf] + r * 512 + ((c ^ (r & 7)) << 4),
                 Kt + (size_t)r * KVD + c * 4);
        }
#pragma unroll
        for (int it = 0; it < 8; it++) {
            int idx = tid + it * 256;
            int r = idx >> 4, c = idx & 15;
            cp16(VSo[buf] + r * 256 + (((uint32_t)c ^ (r & 7)) << 4),
                 Vt + (size_t)r * SEQ + c * 4);
        }
    };
    loadKV(0, 0);
    asm volatile("cp.async.commit_group;" ::: "memory");

    const int wmS = (wid >> 1) * 32, wnS = (wid & 1) * 32;
    const int wmP = (wid >> 1) * 32, wnP = (wid & 1) * 64;
    const uint32_t xr     = lid & 7;
    const uint32_t a_row  = lid & 15;
    const uint32_t a_cadd = (lid >= 16) ? 4u : 0u;
    const uint32_t b_row  = ((lid >> 4) << 3) + (lid & 7);
    const uint32_t b_cadd = ((lid >> 3) & 1) * 4u;

    float oacc[2][8][4];
#pragma unroll
    for (int mi = 0; mi < 2; mi++)
#pragma unroll
        for (int nj = 0; nj < 8; nj++)
#pragma unroll
            for (int r = 0; r < 4; r++) oacc[mi][nj][r] = 0.f;

    for (int t = 0; t < SEQ / 64; t++) {
        const int buf = t & 1;
        // All warps must be done with buf^1 (prev iteration's PV reads)
        // BEFORE we overwrite it with the next tile's cp.async.
        __syncthreads();
        if (t + 1 < SEQ / 64) {
            loadKV(buf ^ 1, t + 1);
            asm volatile("cp.async.commit_group;" ::: "memory");
            asm volatile("cp.async.wait_group 1;" ::: "memory");
        } else {
            asm volatile("cp.async.wait_group 0;" ::: "memory");
        }
        __syncthreads();

        // ---- S = Q K^T (warp 32x32, k=128) ----
        float sacc[2][4][4];
#pragma unroll
        for (int mi = 0; mi < 2; mi++)
#pragma unroll
            for (int nj = 0; nj < 4; nj++)
#pragma unroll
                for (int r = 0; r < 4; r++) sacc[mi][nj][r] = 0.f;

#pragma unroll
        for (int ks = 0; ks < 16; ks++) {
            const int k0 = ks * 8;
            uint32_t ar[2][4];
#pragma unroll
            for (int mi = 0; mi < 2; mi++) {
                uint32_t addr = sb + AS_QS + (wmS + mi * 16 + a_row) * 512
                              + ((((k0 + a_cadd) >> 2) ^ xr) << 4);
                LDSM_X4(ar[mi][0], ar[mi][1], ar[mi][2], ar[mi][3], addr);
            }
            uint32_t br[2][4];
#pragma unroll
            for (int nb = 0; nb < 2; nb++) {
                uint32_t addr = KSo[buf] + (wnS + nb * 16 + b_row) * 512
                              + ((((k0 + b_cadd) >> 2) ^ xr) << 4);
                LDSM_X4(br[nb][0], br[nb][1], br[nb][2], br[nb][3], addr);
            }
#pragma unroll
            for (int mi = 0; mi < 2; mi++)
#pragma unroll
                for (int nj = 0; nj < 4; nj++)
                    MMA_TF32(sacc[mi][nj], ar[mi][0], ar[mi][1], ar[mi][2], ar[mi][3],
                             br[nj >> 1][(nj & 1) * 2], br[nj >> 1][(nj & 1) * 2 + 1]);
        }

        // store S (scaled) to Ss: 128 rows x 256B, swizzled 16B chunks
#pragma unroll
        for (int mi = 0; mi < 2; mi++) {
            int r0 = wmS + mi * 16 + (lid >> 2);
#pragma unroll
            for (int nj = 0; nj < 4; nj++) {
                int col = wnS + nj * 8 + 2 * (lid & 3);
                uint32_t off = (((uint32_t)(col >> 2) ^ (r0 & 7)) << 4) + (col & 3) * 4;
                *(float2*)(smb + AS_SS + r0 * 256 + off) =
                    make_float2(sacc[mi][nj][0] * SOFTMAX_SCALE, sacc[mi][nj][1] * SOFTMAX_SCALE);
                int r1 = r0 + 8;
                uint32_t off1 = (((uint32_t)(col >> 2) ^ (r1 & 7)) << 4) + (col & 3) * 4;
                *(float2*)(smb + AS_SS + r1 * 256 + off1) =
                    make_float2(sacc[mi][nj][2] * SOFTMAX_SCALE, sacc[mi][nj][3] * SOFTMAX_SCALE);
            }
        }
        __syncthreads();

        // ---- online softmax: 2 threads per row (128 rows); P tf32-rounded ----
        {
            const int r = tid >> 1, seg = tid & 1;
            float4 v[8];
            uint32_t base = (uint32_t)AS_SS + r * 256;
#pragma unroll
            for (int j = 0; j < 8; j++) {
                uint32_t c = (uint32_t)(seg * 8 + j) ^ (r & 7);
                v[j] = *(const float4*)(smb + base + (c << 4));
            }
            float mx = -INFINITY;
#pragma unroll
            for (int j = 0; j < 8; j++)
                mx = fmaxf(mx, fmaxf(fmaxf(v[j].x, v[j].y), fmaxf(v[j].z, v[j].w)));
            mx = fmaxf(mx, __shfl_xor_sync(0xFFFFFFFFu, mx, 1));
            float m_old = row_m[r];
            float mn = fmaxf(m_old, mx);
            float sum = 0.f;
#pragma unroll
            for (int j = 0; j < 8; j++) {
                v[j].x = __expf(v[j].x - mn);
                v[j].y = __expf(v[j].y - mn);
                v[j].z = __expf(v[j].z - mn);
                v[j].w = __expf(v[j].w - mn);
                sum += v[j].x + v[j].y + v[j].z + v[j].w;
                v[j].x = f2tf32(v[j].x); v[j].y = f2tf32(v[j].y);
                v[j].z = f2tf32(v[j].z); v[j].w = f2tf32(v[j].w);
                uint32_t c = (uint32_t)(seg * 8 + j) ^ (r & 7);
                *(float4*)(smb + base + (c << 4)) = v[j];
            }
            sum += __shfl_xor_sync(0xFFFFFFFFu, sum, 1);
            if (seg == 0) {
                float f = __expf(m_old - mn);
                row_m[r] = mn;
                row_f[r] = f;
                row_l[r] = row_l[r] * f + sum;
            }
        }
        __syncthreads();

        // ---- rescale O accumulator, then O += P V ----
        {
            float f0[2], f1[2];
#pragma unroll
            for (int mi = 0; mi < 2; mi++) {
                f0[mi] = row_f[wmP + mi * 16 + (lid >> 2)];
                f1[mi] = row_f[wmP + mi * 16 + (lid >> 2) + 8];
            }
#pragma unroll
            for (int mi = 0; mi < 2; mi++)
#pragma unroll
                for (int nj = 0; nj < 8; nj++) {
                    oacc[mi][nj][0] *= f0[mi]; oacc[mi][nj][1] *= f0[mi];
                    oacc[mi][nj][2] *= f1[mi]; oacc[mi][nj][3] *= f1[mi];
                }
        }
#pragma unroll
        for (int ks = 0; ks < 8; ks++) {
            const int k0 = ks * 8;
            uint32_t ar[2][4];
#pragma unroll
            for (int mi = 0; mi < 2; mi++) {
                uint32_t addr = sb + AS_SS + (wmP + mi * 16 + a_row) * 256
                              + ((((k0 + a_cadd) >> 2) ^ xr) << 4);
                LDSM_X4(ar[mi][0], ar[mi][1], ar[mi][2], ar[mi][3], addr);
            }
            uint32_t br[4][4];
#pragma unroll
            for (int nb = 0; nb < 4; nb++) {
                uint32_t addr = VSo[buf] + (wnP + nb * 16 + b_row) * 256
                              + ((((k0 + b_cadd) >> 2) ^ xr) << 4);
                LDSM_X4(br[nb][0], br[nb][1], br[nb][2], br[nb][3], addr);
            }
#pragma unroll
            for (int mi = 0; mi < 2; mi++)
#pragma unroll
                for (int nj = 0; nj < 8; nj++)
                    MMA_TF32(oacc[mi][nj], ar[mi][0], ar[mi][1], ar[mi][2], ar[mi][3],
                             br[nj >> 1][(nj & 1) * 2], br[nj >> 1][(nj & 1) * 2 + 1]);
        }
    }

    // ---- epilogue: normalize, round to tf32 (feeds O-proj A operand) ----
#pragma unroll
    for (int mi = 0; mi < 2; mi++) {
        int lr0 = wmP + mi * 16 + (lid >> 2);
        float inv0 = 1.0f / row_l[lr0];
        float inv1 = 1.0f / row_l[lr0 + 8];
        float* O0 = g_O + (size_t)(b * SEQ + q0 + lr0) * DMODEL + h * HDIM;
        float* O1 = g_O + (size_t)(b * SEQ + q0 + lr0 + 8) * DMODEL + h * HDIM;
#pragma unroll
        for (int nj = 0; nj < 8; nj++) {
            int col = wnP + nj * 8 + 2 * (lid & 3);
            *(float2*)(O0 + col) = make_float2(f2tf32(oacc[mi][nj][0] * inv0),
                                               f2tf32(oacc[mi][nj][1] * inv0));
            *(float2*)(O1 + col) = make_float2(f2tf32(oacc[mi][nj][2] * inv1),
                                               f2tf32(oacc[mi][nj][3] * inv1));
        }
    }
}

// ---------------------------------------------------------------------------
extern "C" void kernel_launch(void* const* d_in, const int* in_sizes, int n_in,
                              void* d_out, int out_size)
{
    const float* x  = (const float*)d_in[0];
    const float* Wq = (const float*)d_in[1];
    const float* bq = (const float*)d_in[2];
    const float* Wk = (const float*)d_in[3];
    const float* bk = (const float*)d_in[4];
    const float* Wv = (const float*)d_in[5];
    const float* bv = (const float*)d_in[6];
    const float* Wo = (const float*)d_in[7];
    const float* bo = (const float*)d_in[8];
    float* out = (float*)d_out;

    float *Q, *K, *V, *Vt, *O, *WqT, *WkT, *WvT, *WoT;
    cudaGetSymbolAddress((void**)&Q, g_Q);
    cudaGetSymbolAddress((void**)&K, g_K);
    cudaGetSymbolAddress((void**)&V, g_V);
    cudaGetSymbolAddress((void**)&Vt, g_Vt);
    cudaGetSymbolAddress((void**)&O, g_O);
    cudaGetSymbolAddress((void**)&WqT, g_WqT);
    cudaGetSymbolAddress((void**)&WkT, g_WkT);
    cudaGetSymbolAddress((void**)&WvT, g_WvT);
    cudaGetSymbolAddress((void**)&WoT, g_WoT);

    cudaFuncSetAttribute(tf32_mma_gemm,
                         cudaFuncAttributeMaxDynamicSharedMemorySize, GM_SMEM);
    cudaFuncSetAttribute(attn_mma_kernel,
                         cudaFuncAttributeMaxDynamicSharedMemorySize, ATT_SMEM);

    // Transpose weights to [N][K] (tf32-rounded)
    transpose_kernel<<<dim3(DMODEL/32, DMODEL/32), dim3(32, 8)>>>(Wq, WqT, DMODEL, DMODEL);
    transpose_kernel<<<dim3(KVD/32,    DMODEL/32), dim3(32, 8)>>>(Wk, WkT, DMODEL, KVD);
    transpose_kernel<<<dim3(KVD/32,    DMODEL/32), dim3(32, 8)>>>(Wv, WvT, DMODEL, KVD);
    transpose_kernel<<<dim3(DMODEL/32, DMODEL/32), dim3(32, 8)>>>(Wo, WoT, DMODEL, DMODEL);

    // Round x to tf32 into g_O (free until attention writes it)
    round_copy_kernel<<<(ROWS * DMODEL / 4 + 255) / 256, 256>>>(
        (const float4*)x, (float4*)O, ROWS * DMODEL / 4);

    // Q/K projections with fused RoPE (+round); V projection (+round)
    tf32_mma_gemm<<<dim3(DMODEL/128, ROWS/128), 256, GM_SMEM>>>(O, WqT, bq, Q, ROWS, DMODEL, DMODEL, 2, SOFTMAX_SCALE);
    tf32_mma_gemm<<<dim3(KVD/128,    ROWS/128), 256, GM_SMEM>>>(O, WkT, bk, K, ROWS, KVD, DMODEL, 2, 1.0f);
    tf32_mma_gemm<<<dim3(KVD/128,    ROWS/128), 256, GM_SMEM>>>(O, WvT, bv, V, ROWS, KVD, DMODEL, 1, 1.0f);

    // Transpose V per (b,g) to [dim][seq] for ldmatrix-friendly PV
    v_transpose_kernel<<<dim3(KVD/32, ROWS/32), dim3(32, 8)>>>(V, Vt);

    // Attention (tf32 mma flash, 128-q tiles); writes tf32-rounded O into g_O
    attn_mma_kernel<<<dim3(BATCH * NHEADS, SEQ / 128), 256, ATT_SMEM>>>();

    // Output projection (final fp32 output, no rounding)
    tf32_mma_gemm<<<dim3(DMODEL/128, ROWS/128), 256, GM_SMEM>>>(O, WoT, bo, out, ROWS, DMODEL, DMODEL, 0, 1.0f);
}